// round 11
// baseline (speedup 1.0000x reference)
#include <cuda_runtime.h>
#include <cuda_bf16.h>
#include <cstdint>
#include <math.h>

// Problem constants
#define NB     16
#define NC     512
#define NHW    1024
#define NHEADS 8
#define ND     64
#define QC     1536     // 3*NC
#define GN_EPS 1e-5f

// ===========================================================================
// Warp-level MMA helpers (sm_80+ paths — legal on base sm_100)
// ===========================================================================
__device__ __forceinline__ uint32_t smem_to_u32(const void* p) {
    uint32_t a;
    asm("{ .reg .u64 t; cvta.to.shared.u64 t, %1; cvt.u32.u64 %0, t; }" : "=r"(a) : "l"(p));
    return a;
}
__device__ __forceinline__ void ldsm4(uint32_t* r, uint32_t addr) {
    asm volatile("ldmatrix.sync.aligned.m8n8.x4.shared.b16 {%0,%1,%2,%3}, [%4];"
                 : "=r"(r[0]), "=r"(r[1]), "=r"(r[2]), "=r"(r[3]) : "r"(addr));
}
__device__ __forceinline__ void ldsm4t(uint32_t* r, uint32_t addr) {
    asm volatile("ldmatrix.sync.aligned.m8n8.x4.trans.shared.b16 {%0,%1,%2,%3}, [%4];"
                 : "=r"(r[0]), "=r"(r[1]), "=r"(r[2]), "=r"(r[3]) : "r"(addr));
}
__device__ __forceinline__ void mma_bf16(float* d, const uint32_t* a, const uint32_t* b) {
    asm volatile("mma.sync.aligned.m16n8k16.row.col.f32.bf16.bf16.f32 "
                 "{%0,%1,%2,%3}, {%4,%5,%6,%7}, {%8,%9}, {%0,%1,%2,%3};"
                 : "+f"(d[0]), "+f"(d[1]), "+f"(d[2]), "+f"(d[3])
                 : "r"(a[0]), "r"(a[1]), "r"(a[2]), "r"(a[3]), "r"(b[0]), "r"(b[1]));
}
__device__ __forceinline__ void mma4(float* d, uint32_t a0, uint32_t a1, uint32_t a2,
                                     uint32_t a3, uint32_t b0, uint32_t b1) {
    asm volatile("mma.sync.aligned.m16n8k16.row.col.f32.bf16.bf16.f32 "
                 "{%0,%1,%2,%3}, {%4,%5,%6,%7}, {%8,%9}, {%0,%1,%2,%3};"
                 : "+f"(d[0]), "+f"(d[1]), "+f"(d[2]), "+f"(d[3])
                 : "r"(a0), "r"(a1), "r"(a2), "r"(a3), "r"(b0), "r"(b1));
}
__device__ __forceinline__ void cp_async16(uint32_t daddr, const void* g) {
    asm volatile("cp.async.cg.shared.global [%0], [%1], 16;" :: "r"(daddr), "l"(g));
}
#define CP_COMMIT() asm volatile("cp.async.commit_group;" ::: "memory")
#define CP_WAIT(N)  asm volatile("cp.async.wait_group %0;" :: "n"(N) : "memory")

// pack two fp32 -> bf16x2 (element0 in low half)
__device__ __forceinline__ uint32_t packbf(float lo, float hi) {
    uint32_t r;
    asm("cvt.rn.bf16x2.f32 %0, %1, %2;" : "=r"(r) : "f"(hi), "f"(lo));
    return r;
}

// ===========================================================================
// Scratch (device globals — no allocation allowed)
// ===========================================================================
__device__ __nv_bfloat16 g_xh [NB * NHW * NC];       // gn out hi [b][n][c]
__device__ __nv_bfloat16 g_xl [NB * NHW * NC];       // gn out lo
__device__ __nv_bfloat16 g_aoh[NB * NHW * NC];       // attn out hi [b][n][c]
__device__ __nv_bfloat16 g_aol[NB * NHW * NC];       // attn out lo
__device__ __nv_bfloat16 g_qkvh[NB * QC * NHW];      // qkv hi [b][o][n] (Q pre-scaled)
__device__ __nv_bfloat16 g_qkvl[NB * QC * NHW];      // qkv lo
__device__ __nv_bfloat16 g_qwh[QC * NC];             // qkv_w hi  [o][c]
__device__ __nv_bfloat16 g_qwl[QC * NC];
__device__ __nv_bfloat16 g_pwh[NC * NC];             // proj_w hi
__device__ __nv_bfloat16 g_pwl[NC * NC];

// ---------------------------------------------------------------------------
// Kernel 1: GroupNorm fused with transpose+bf16 hi/lo convert.
// ---------------------------------------------------------------------------
__global__ __launch_bounds__(512) void gn_convert(const float* __restrict__ x,
                                                  const float* __restrict__ gw,
                                                  const float* __restrict__ gb,
                                                  __nv_bfloat16* __restrict__ dh,
                                                  __nv_bfloat16* __restrict__ dl) {
    int bg = blockIdx.x;
    int b = bg >> 3, g = bg & 7;
    const float* xp = x + (size_t)(b * NC + g * 64) * NHW;
    const int NE4 = 64 * NHW / 4;
    int tid = threadIdx.x;

    float s = 0.f, s2 = 0.f;
    const float4* xp4 = (const float4*)xp;
    for (int i = tid; i < NE4; i += 512) {
        float4 v = xp4[i];
        s  += v.x + v.y + v.z + v.w;
        s2 += v.x * v.x + v.y * v.y + v.z * v.z + v.w * v.w;
    }
    __shared__ float rs[16], rs2[16];
    #pragma unroll
    for (int o = 16; o > 0; o >>= 1) {
        s  += __shfl_down_sync(0xFFFFFFFFu, s, o);
        s2 += __shfl_down_sync(0xFFFFFFFFu, s2, o);
    }
    int w = tid >> 5, l = tid & 31;
    if (l == 0) { rs[w] = s; rs2[w] = s2; }
    __syncthreads();
    __shared__ float sh_mean, sh_rstd;
    if (tid == 0) {
        float S = 0.f, S2 = 0.f;
        #pragma unroll
        for (int i = 0; i < 16; i++) { S += rs[i]; S2 += rs2[i]; }
        float mean = S * (1.f / 65536.f);
        float var  = S2 * (1.f / 65536.f) - mean * mean;
        sh_mean = mean;
        sh_rstd = rsqrtf(var + GN_EPS);
    }
    __syncthreads();
    float mean = sh_mean, rstd = sh_rstd;

    __shared__ float t[64][33];
    int tcol = tid & 31, trow = tid >> 5;
    int n_l  = tid >> 4;
    int cseg = (tid & 15) * 4;
    float sc[4], bi[4];
    #pragma unroll
    for (int i = 0; i < 4; i++) {
        int c = g * 64 + cseg + i;
        sc[i] = gw[c] * rstd;
        bi[i] = gb[c] - mean * sc[i];
    }

    for (int n0 = 0; n0 < NHW; n0 += 32) {
        __syncthreads();
        #pragma unroll
        for (int i = 0; i < 4; i++) {
            int c = trow + i * 16;
            t[c][tcol] = xp[(size_t)c * NHW + n0 + tcol];
        }
        __syncthreads();
        float f0 = t[cseg + 0][n_l] * sc[0] + bi[0];
        float f1 = t[cseg + 1][n_l] * sc[1] + bi[1];
        float f2 = t[cseg + 2][n_l] * sc[2] + bi[2];
        float f3 = t[cseg + 3][n_l] * sc[3] + bi[3];
        uint32_t h0 = packbf(f0, f1), h1 = packbf(f2, f3);
        uint32_t l0 = packbf(f0 - __uint_as_float(h0 << 16),
                             f1 - __uint_as_float(h0 & 0xFFFF0000u));
        uint32_t l1 = packbf(f2 - __uint_as_float(h1 << 16),
                             f3 - __uint_as_float(h1 & 0xFFFF0000u));
        size_t ob = ((size_t)b * NHW + n0 + n_l) * NC + g * 64 + cseg;
        *(uint2*)(dh + ob) = make_uint2(h0, h1);
        *(uint2*)(dl + ob) = make_uint2(l0, l1);
    }
}

// ---------------------------------------------------------------------------
// Convert weights fp32 -> bf16 hi/lo (same layout)
// ---------------------------------------------------------------------------
__global__ void convert_w(const float* __restrict__ src, __nv_bfloat16* __restrict__ dh,
                          __nv_bfloat16* __restrict__ dl, int n) {
    int i = blockIdx.x * 256 + threadIdx.x;
    if (i < n) {
        float v = src[i];
        __nv_bfloat16 h = __float2bfloat16(v);
        dh[i] = h;
        dl[i] = __float2bfloat16(v - __bfloat162float(h));
    }
}

// ---------------------------------------------------------------------------
// QKV GEMM v6 (experiment): CTA 128(o) x 64(n), 8 warps (2o x 4n),
// warp tile 64x16 -> acc 32 regs/thread (~100 total). 256 threads,
// 2 CTAs/SM -> 16 warps/SM (attention's occupancy). k-chunk 64, 2-stage,
// 144B-padded rows, 108KB smem.
// ---------------------------------------------------------------------------
#define G6_ROW    144
#define G6_A_TILE (128 * G6_ROW)            // 18432
#define G6_B_TILE (64 * G6_ROW)             // 9216
#define G6_STAGE  (2 * G6_A_TILE + 2 * G6_B_TILE)   // 55296
#define G6_SMEM   (2 * G6_STAGE)                    // 110592

__global__ __launch_bounds__(256, 2) void qkv_gemm6(
        const __nv_bfloat16* __restrict__ Ah, const __nv_bfloat16* __restrict__ Al,
        const __nv_bfloat16* __restrict__ Bh, const __nv_bfloat16* __restrict__ Bl,
        const float* __restrict__ bias,
        __nv_bfloat16* __restrict__ outh, __nv_bfloat16* __restrict__ outl) {
    extern __shared__ char smem[];
    uint32_t smem_u = smem_to_u32(smem);
    int tid = threadIdx.x;
    int warp = tid >> 5, lane = tid & 31;
    int wm = warp & 1, wn = warp >> 1;      // 2(o) x 4(n)
    int n0 = blockIdx.x * 64;
    int o0 = blockIdx.y * 128;
    int b  = blockIdx.z;

    const __nv_bfloat16* a0 = Ah + (size_t)o0 * NC;
    const __nv_bfloat16* a1 = Al + (size_t)o0 * NC;
    const __nv_bfloat16* b0 = Bh + ((size_t)b * NHW + n0) * NC;
    const __nv_bfloat16* b1 = Bl + ((size_t)b * NHW + n0) * NC;

    auto load_stage = [&](int chunk, int s) {
        int k0 = chunk * 64;
        uint32_t sbase = smem_u + s * G6_STAGE;
        #pragma unroll
        for (int t = 0; t < 8; t++) {        // A hi/lo: 2048 cp
            int idx = t * 256 + tid;
            int tile = idx >> 10;
            int r = (idx >> 3) & 127;
            int ch = idx & 7;
            const __nv_bfloat16* src = tile ? a1 : a0;
            cp_async16(sbase + tile * G6_A_TILE + r * G6_ROW + ch * 16,
                       src + (size_t)r * NC + k0 + ch * 8);
        }
        #pragma unroll
        for (int t = 0; t < 4; t++) {        // B hi/lo: 1024 cp
            int idx = t * 256 + tid;
            int tile = idx >> 9;
            int r = (idx >> 3) & 63;
            int ch = idx & 7;
            const __nv_bfloat16* src = tile ? b1 : b0;
            cp_async16(sbase + 2 * G6_A_TILE + tile * G6_B_TILE + r * G6_ROW + ch * 16,
                       src + (size_t)r * NC + k0 + ch * 8);
        }
        CP_COMMIT();
    };

    float acc[4][2][4] = {};
    uint32_t aLane = (uint32_t)((lane & 15) * G6_ROW + (lane >> 4) * 16);
    uint32_t bLane = (uint32_t)(((lane & 7) + ((lane >> 4) << 3)) * G6_ROW +
                                ((lane >> 3) & 1) * 16);

    load_stage(0, 0);
    #pragma unroll 1
    for (int c = 0; c < 8; c++) {
        if (c + 1 < 8) { load_stage(c + 1, (c + 1) & 1); CP_WAIT(1); }
        else { CP_WAIT(0); }
        __syncthreads();

        uint32_t sb = smem_u + (c & 1) * G6_STAGE;
        uint32_t offAh = sb                 + (wm * 64) * G6_ROW + aLane;
        uint32_t offAl = offAh + G6_A_TILE;
        uint32_t offBh = sb + 2 * G6_A_TILE + (wn * 16) * G6_ROW + bLane;
        uint32_t offBl = offBh + G6_B_TILE;

        #pragma unroll
        for (int ks = 0; ks < 4; ks++) {
            uint32_t ko = ks * 32;           // 16 bf16 = 32 bytes
            uint32_t af[4][4], bh[4], bl[4];
            #pragma unroll
            for (int i = 0; i < 4; i++) ldsm4(af[i], offAh + i * 16 * G6_ROW + ko);
            ldsm4(bh, offBh + ko);
            ldsm4(bl, offBl + ko);
            #pragma unroll
            for (int i = 0; i < 4; i++) {
                mma_bf16(acc[i][0], af[i], &bh[0]);
                mma_bf16(acc[i][1], af[i], &bh[2]);
            }
            #pragma unroll
            for (int i = 0; i < 4; i++) {
                mma_bf16(acc[i][0], af[i], &bl[0]);
                mma_bf16(acc[i][1], af[i], &bl[2]);
            }
            #pragma unroll
            for (int i = 0; i < 4; i++) ldsm4(af[i], offAl + i * 16 * G6_ROW + ko);
            #pragma unroll
            for (int i = 0; i < 4; i++) {
                mma_bf16(acc[i][0], af[i], &bh[0]);
                mma_bf16(acc[i][1], af[i], &bh[2]);
            }
        }
        __syncthreads();
    }

    // Epilogue: bf16 hi/lo, Q rows scaled by 0.125
    int r0 = lane >> 2, c0 = (lane & 3) * 2;
    #pragma unroll
    for (int i = 0; i < 4; i++) {
        #pragma unroll
        for (int half = 0; half < 2; half++) {
            int o = o0 + wm * 64 + i * 16 + r0 + half * 8;
            float bi = bias[o];
            float scq = (o < NC) ? 0.125f : 1.0f;
            size_t rowb = ((size_t)b * QC + o) * NHW + n0 + wn * 16 + c0;
            #pragma unroll
            for (int j = 0; j < 2; j++) {
                float v0 = (acc[i][j][half * 2]     + bi) * scq;
                float v1 = (acc[i][j][half * 2 + 1] + bi) * scq;
                uint32_t hp = packbf(v0, v1);
                uint32_t lp = packbf(v0 - __uint_as_float(hp << 16),
                                     v1 - __uint_as_float(hp & 0xFFFF0000u));
                *(uint32_t*)(outh + rowb + j * 8) = hp;
                *(uint32_t*)(outl + rowb + j * 8) = lp;
            }
        }
    }
}

// ---------------------------------------------------------------------------
// Proj GEMM v3 (R9 control, unchanged): CTA 128x128, 4 warps 64x64, 2-stage.
// ---------------------------------------------------------------------------
#define G3_TILE_B  10240              // 128 rows x 80B
#define G3_STAGE_B (4 * G3_TILE_B)    // 40960
#define G3_SMEM    (2 * G3_STAGE_B)   // 81920

__global__ __launch_bounds__(128, 2) void proj_gemm3(
        const __nv_bfloat16* __restrict__ Ah, const __nv_bfloat16* __restrict__ Al,
        const __nv_bfloat16* __restrict__ Bh, const __nv_bfloat16* __restrict__ Bl,
        const float* __restrict__ bias, const float* __restrict__ residual,
        float* __restrict__ out) {
    extern __shared__ char smem[];
    uint32_t smem_u = smem_to_u32(smem);
    int tid = threadIdx.x;
    int warp = tid >> 5, lane = tid & 31;
    int wm = warp & 1, wn = warp >> 1;
    int n0 = blockIdx.x * 128;
    int o0 = blockIdx.y * 128;
    int b  = blockIdx.z;

    const __nv_bfloat16* a0 = Ah + (size_t)o0 * NC;
    const __nv_bfloat16* a1 = Al + (size_t)o0 * NC;
    const __nv_bfloat16* b0 = Bh + ((size_t)b * NHW + n0) * NC;
    const __nv_bfloat16* b1 = Bl + ((size_t)b * NHW + n0) * NC;
    const __nv_bfloat16* srcs[4] = {a0, a1, b0, b1};

    auto load_stage = [&](int chunk, int s) {
        int k0 = chunk * 32;
        uint32_t sbase = smem_u + s * G3_STAGE_B;
        #pragma unroll
        for (int t = 0; t < 16; t++) {
            int idx = t * 128 + tid;
            int tile = idx >> 9;
            int r = (idx >> 2) & 127;
            int ch = idx & 3;
            cp_async16(sbase + tile * G3_TILE_B + r * 80 + ch * 16,
                       srcs[tile] + (size_t)r * NC + k0 + ch * 8);
        }
        CP_COMMIT();
    };

    float acc[4][8][4] = {};
    uint32_t aLane = (uint32_t)((lane & 15) * 80 + (lane >> 4) * 16);
    uint32_t bLane = (uint32_t)(((lane & 7) + ((lane >> 4) << 3)) * 80 +
                                ((lane >> 3) & 1) * 16);
    load_stage(0, 0);
    #pragma unroll 1
    for (int c = 0; c < 16; c++) {
        if (c + 1 < 16) { load_stage(c + 1, (c + 1) & 1); CP_WAIT(1); }
        else { CP_WAIT(0); }
        __syncthreads();
        uint32_t sb = smem_u + (c & 1) * G3_STAGE_B;
        uint32_t offAh = sb                 + (wm * 64) * 80 + aLane;
        uint32_t offAl = sb + G3_TILE_B     + (wm * 64) * 80 + aLane;
        uint32_t offBh = sb + 2 * G3_TILE_B + (wn * 64) * 80 + bLane;
        uint32_t offBl = offBh + G3_TILE_B;
        #pragma unroll
        for (int ks = 0; ks < 2; ks++) {
            uint32_t ko = ks * 32;
            uint32_t af[4][4], bh[4][4], bl[4][4];
            #pragma unroll
            for (int i = 0; i < 4; i++) ldsm4(af[i], offAh + i * 16 * 80 + ko);
            #pragma unroll
            for (int g = 0; g < 4; g++) ldsm4(bh[g], offBh + g * 16 * 80 + ko);
            #pragma unroll
            for (int g = 0; g < 4; g++) ldsm4(bl[g], offBl + g * 16 * 80 + ko);
            #pragma unroll
            for (int i = 0; i < 4; i++)
                #pragma unroll
                for (int j = 0; j < 8; j++)
                    mma_bf16(acc[i][j], af[i], &bh[j >> 1][(j & 1) * 2]);
            #pragma unroll
            for (int i = 0; i < 4; i++)
                #pragma unroll
                for (int j = 0; j < 8; j++)
                    mma_bf16(acc[i][j], af[i], &bl[j >> 1][(j & 1) * 2]);
            #pragma unroll
            for (int i = 0; i < 4; i++) ldsm4(af[i], offAl + i * 16 * 80 + ko);
            #pragma unroll
            for (int i = 0; i < 4; i++)
                #pragma unroll
                for (int j = 0; j < 8; j++)
                    mma_bf16(acc[i][j], af[i], &bh[j >> 1][(j & 1) * 2]);
        }
        __syncthreads();
    }

    int r0 = lane >> 2, c0 = (lane & 3) * 2;
    #pragma unroll
    for (int i = 0; i < 4; i++) {
        #pragma unroll
        for (int half = 0; half < 2; half++) {
            int o = o0 + wm * 64 + i * 16 + r0 + half * 8;
            float bi = bias[o];
            size_t rowb = ((size_t)b * NC + o) * NHW + n0 + wn * 64 + c0;
            #pragma unroll
            for (int j = 0; j < 8; j++) {
                float v0 = acc[i][j][half * 2]     + bi;
                float v1 = acc[i][j][half * 2 + 1] + bi;
                size_t off = rowb + j * 8;
                float2 rr = *(const float2*)&residual[off];
                *(float2*)&out[off] = make_float2(v0 + rr.x, v1 + rr.y);
            }
        }
    }
}

// ---------------------------------------------------------------------------
// Flash attention via mma.sync, bf16x3 split (unchanged — at mma.sync ceiling)
// ---------------------------------------------------------------------------
#define QSTR 136
#define KSTR 72
#define OSTR 132
#define Q_BYTES   17408
#define KV_TILE_B 9216
#define STAGE0_OFF (2 * Q_BYTES)
#define KV_STAGE_B (4 * KV_TILE_B)
#define ATTN_SMEM (STAGE0_OFF + 2 * KV_STAGE_B)

__global__ __launch_bounds__(256, 2) void attn_mma() {
    extern __shared__ char smem[];
    uint32_t smem_u = smem_to_u32(smem);
    int tid  = threadIdx.x;
    int warp = tid >> 5, lane = tid & 31;
    int wbase = warp * 16;
    int qt = blockIdx.x, h = blockIdx.y, b = blockIdx.z;

    const __nv_bfloat16* gq_h = g_qkvh + ((size_t)b * QC + h * ND) * NHW;
    const __nv_bfloat16* gq_l = g_qkvl + ((size_t)b * QC + h * ND) * NHW;
    const __nv_bfloat16* gk_h = g_qkvh + ((size_t)b * QC + NC + h * ND) * NHW;
    const __nv_bfloat16* gk_l = g_qkvl + ((size_t)b * QC + NC + h * ND) * NHW;
    const __nv_bfloat16* gv_h = g_qkvh + ((size_t)b * QC + 2 * NC + h * ND) * NHW;
    const __nv_bfloat16* gv_l = g_qkvl + ((size_t)b * QC + 2 * NC + h * ND) * NHW;
    const __nv_bfloat16* kvsrc[4] = {gk_h, gk_l, gv_h, gv_l};

    int rowoff = ((lane >> 4) << 3) + (lane & 7);
    int coloff = ((lane >> 3) & 1) * 8;

    auto load_stage = [&](int kt, int s) {
        uint32_t sb = smem_u + STAGE0_OFF + s * KV_STAGE_B;
        #pragma unroll
        for (int k = 0; k < 8; k++) {
            int c = tid + k * 256;
            int tile = c >> 9, row = (c >> 3) & 63, ch = c & 7;
            cp_async16(sb + tile * KV_TILE_B + row * (KSTR * 2) + ch * 16,
                       kvsrc[tile] + (size_t)row * NHW + kt * 64 + ch * 8);
        }
        CP_COMMIT();
    };

    {
        #pragma unroll
        for (int k = 0; k < 8; k++) {
            int c = tid + k * 256;
            int tile = c >> 10, row = (c >> 4) & 63, ch = c & 15;
            const __nv_bfloat16* src = tile ? gq_l : gq_h;
            cp_async16(smem_u + tile * Q_BYTES + row * (QSTR * 2) + ch * 16,
                       src + (size_t)row * NHW + qt * 128 + ch * 8);
        }
    }
    load_stage(0, 0);

    float m0 = -1e30f, m1 = -1e30f, l0 = 0.f, l1 = 0.f;
    float oacc[8][4] = {};

    uint32_t qAddrH = smem_u + (uint32_t)(rowoff * (QSTR * 2) + (wbase + coloff) * 2);
    uint32_t qAddrL = qAddrH + Q_BYTES;

    #pragma unroll 1
    for (int kt = 0; kt < 16; kt++) {
        CP_WAIT(0);
        __syncthreads();
        if (kt < 15) load_stage(kt + 1, (kt + 1) & 1);

        uint32_t sb = smem_u + STAGE0_OFF + (kt & 1) * KV_STAGE_B;
        float sacc[8][4] = {};
        #pragma unroll
        for (int kc = 0; kc < 4; kc++) {
            uint32_t qh[4], ql[4];
            ldsm4t(qh, qAddrH + kc * 16 * (QSTR * 2));
            ldsm4t(ql, qAddrL + kc * 16 * (QSTR * 2));
            uint32_t kBase = sb + (uint32_t)((kc * 16 + rowoff) * (KSTR * 2) + coloff * 2);
            #pragma unroll
            for (int ko2 = 0; ko2 < 4; ko2++) {
                uint32_t kh[4], kl[4];
                ldsm4t(kh, kBase + ko2 * 32);
                ldsm4t(kl, kBase + KV_TILE_B + ko2 * 32);
                mma4(sacc[2*ko2],   qh[0],qh[1],qh[2],qh[3], kh[0], kh[2]);
                mma4(sacc[2*ko2+1], qh[0],qh[1],qh[2],qh[3], kh[1], kh[3]);
                mma4(sacc[2*ko2],   qh[0],qh[1],qh[2],qh[3], kl[0], kl[2]);
                mma4(sacc[2*ko2+1], qh[0],qh[1],qh[2],qh[3], kl[1], kl[3]);
                mma4(sacc[2*ko2],   ql[0],ql[1],ql[2],ql[3], kh[0], kh[2]);
                mma4(sacc[2*ko2+1], ql[0],ql[1],ql[2],ql[3], kh[1], kh[3]);
            }
        }

        float tm0 = -1e30f, tm1 = -1e30f;
        #pragma unroll
        for (int j = 0; j < 8; j++) {
            tm0 = fmaxf(tm0, fmaxf(sacc[j][0], sacc[j][1]));
            tm1 = fmaxf(tm1, fmaxf(sacc[j][2], sacc[j][3]));
        }
        tm0 = fmaxf(tm0, __shfl_xor_sync(0xFFFFFFFFu, tm0, 1));
        tm0 = fmaxf(tm0, __shfl_xor_sync(0xFFFFFFFFu, tm0, 2));
        tm1 = fmaxf(tm1, __shfl_xor_sync(0xFFFFFFFFu, tm1, 1));
        tm1 = fmaxf(tm1, __shfl_xor_sync(0xFFFFFFFFu, tm1, 2));
        float nm0 = fmaxf(m0, tm0), nm1 = fmaxf(m1, tm1);
        float al0 = __expf(m0 - nm0), al1 = __expf(m1 - nm1);
        m0 = nm0; m1 = nm1;
        float sum0 = 0.f, sum1 = 0.f;
        #pragma unroll
        for (int j = 0; j < 8; j++) {
            sacc[j][0] = __expf(sacc[j][0] - m0); sum0 += sacc[j][0];
            sacc[j][1] = __expf(sacc[j][1] - m0); sum0 += sacc[j][1];
            sacc[j][2] = __expf(sacc[j][2] - m1); sum1 += sacc[j][2];
            sacc[j][3] = __expf(sacc[j][3] - m1); sum1 += sacc[j][3];
        }
        sum0 += __shfl_xor_sync(0xFFFFFFFFu, sum0, 1);
        sum0 += __shfl_xor_sync(0xFFFFFFFFu, sum0, 2);
        sum1 += __shfl_xor_sync(0xFFFFFFFFu, sum1, 1);
        sum1 += __shfl_xor_sync(0xFFFFFFFFu, sum1, 2);
        l0 = l0 * al0 + sum0;
        l1 = l1 * al1 + sum1;
        #pragma unroll
        for (int d = 0; d < 8; d++) {
            oacc[d][0] *= al0; oacc[d][1] *= al0;
            oacc[d][2] *= al1; oacc[d][3] *= al1;
        }

        uint32_t vB = sb + 2 * KV_TILE_B;
        #pragma unroll
        for (int kc2 = 0; kc2 < 4; kc2++) {
            int j0 = 2 * kc2, j1 = j0 + 1;
            uint32_t pa0 = packbf(sacc[j0][0], sacc[j0][1]);
            uint32_t pa1 = packbf(sacc[j0][2], sacc[j0][3]);
            uint32_t pa2 = packbf(sacc[j1][0], sacc[j1][1]);
            uint32_t pa3 = packbf(sacc[j1][2], sacc[j1][3]);
            uint32_t pl0 = packbf(sacc[j0][0] - __uint_as_float(pa0 << 16),
                                  sacc[j0][1] - __uint_as_float(pa0 & 0xFFFF0000u));
            uint32_t pl1 = packbf(sacc[j0][2] - __uint_as_float(pa1 << 16),
                                  sacc[j0][3] - __uint_as_float(pa1 & 0xFFFF0000u));
            uint32_t pl2 = packbf(sacc[j1][0] - __uint_as_float(pa2 << 16),
                                  sacc[j1][1] - __uint_as_float(pa2 & 0xFFFF0000u));
            uint32_t pl3 = packbf(sacc[j1][2] - __uint_as_float(pa3 << 16),
                                  sacc[j1][3] - __uint_as_float(pa3 & 0xFFFF0000u));
            uint32_t vCol = (uint32_t)((kc2 * 16 + coloff) * 2);
            #pragma unroll
            for (int do2 = 0; do2 < 4; do2++) {
                uint32_t vh[4], vl[4];
                uint32_t vRow = (uint32_t)((do2 * 16 + rowoff) * (KSTR * 2));
                ldsm4(vh, vB + vRow + vCol);
                ldsm4(vl, vB + KV_TILE_B + vRow + vCol);
                mma4(oacc[2*do2],   pa0,pa1,pa2,pa3, vh[0], vh[1]);
                mma4(oacc[2*do2+1], pa0,pa1,pa2,pa3, vh[2], vh[3]);
                mma4(oacc[2*do2],   pl0,pl1,pl2,pl3, vh[0], vh[1]);
                mma4(oacc[2*do2+1], pl0,pl1,pl2,pl3, vh[2], vh[3]);
                mma4(oacc[2*do2],   pa0,pa1,pa2,pa3, vl[0], vl[1]);
                mma4(oacc[2*do2+1], pa0,pa1,pa2,pa3, vl[2], vl[3]);
            }
        }
    }

    float* Os = (float*)(smem + STAGE0_OFF);
    float linv0 = 1.f / l0, linv1 = 1.f / l1;
    int r0q = wbase + (lane >> 2);
    int ddc = (lane & 3) * 2;
    #pragma unroll
    for (int d = 0; d < 8; d++) {
        Os[(d * 8 + ddc)     * OSTR + r0q]     = oacc[d][0] * linv0;
        Os[(d * 8 + ddc + 1) * OSTR + r0q]     = oacc[d][1] * linv0;
        Os[(d * 8 + ddc)     * OSTR + r0q + 8] = oacc[d][2] * linv1;
        Os[(d * 8 + ddc + 1) * OSTR + r0q + 8] = oacc[d][3] * linv1;
    }
    __syncthreads();

    {
        int q = tid >> 1;
        int ddb = (tid & 1) * 32;
        uint32_t hb[16], lb[16];
        #pragma unroll
        for (int d = 0; d < 32; d += 2) {
            float f0 = Os[(ddb + d)     * OSTR + q];
            float f1 = Os[(ddb + d + 1) * OSTR + q];
            uint32_t hp = packbf(f0, f1);
            hb[d >> 1] = hp;
            lb[d >> 1] = packbf(f0 - __uint_as_float(hp << 16),
                                f1 - __uint_as_float(hp & 0xFFFF0000u));
        }
        size_t base = ((size_t)b * NHW + qt * 128 + q) * NC + h * 64 + ddb;
        #pragma unroll
        for (int u = 0; u < 4; u++) {
            *(uint4*)(g_aoh + base + u * 8) = *(uint4*)&hb[u * 4];
            *(uint4*)(g_aol + base + u * 8) = *(uint4*)&lb[u * 4];
        }
    }
}

// ---------------------------------------------------------------------------
extern "C" void kernel_launch(void* const* d_in, const int* in_sizes, int n_in,
                              void* d_out, int out_size) {
    const float* x      = (const float*)d_in[0];
    const float* gn_w   = (const float*)d_in[1];
    const float* gn_b   = (const float*)d_in[2];
    const float* qkv_w  = (const float*)d_in[3];
    const float* qkv_b  = (const float*)d_in[4];
    const float* proj_w = (const float*)d_in[5];
    const float* proj_b = (const float*)d_in[6];
    float* out = (float*)d_out;

    cudaFuncSetAttribute(qkv_gemm6, cudaFuncAttributeMaxDynamicSharedMemorySize, G6_SMEM);
    cudaFuncSetAttribute(proj_gemm3, cudaFuncAttributeMaxDynamicSharedMemorySize, G3_SMEM);
    cudaFuncSetAttribute(attn_mma, cudaFuncAttributeMaxDynamicSharedMemorySize, ATTN_SMEM);

    __nv_bfloat16 *qwh, *qwl, *pwh, *pwl, *xh, *xl, *aoh, *aol, *qkvh, *qkvl;
    cudaGetSymbolAddress((void**)&qwh, g_qwh);
    cudaGetSymbolAddress((void**)&qwl, g_qwl);
    cudaGetSymbolAddress((void**)&pwh, g_pwh);
    cudaGetSymbolAddress((void**)&pwl, g_pwl);
    cudaGetSymbolAddress((void**)&xh,  g_xh);
    cudaGetSymbolAddress((void**)&xl,  g_xl);
    cudaGetSymbolAddress((void**)&aoh, g_aoh);
    cudaGetSymbolAddress((void**)&aol, g_aol);
    cudaGetSymbolAddress((void**)&qkvh, g_qkvh);
    cudaGetSymbolAddress((void**)&qkvl, g_qkvl);

    // 1. GroupNorm fused with transpose+bf16 convert -> g_xh/g_xl [b][n][c]
    gn_convert<<<NB * 8, 512>>>(x, gn_w, gn_b, xh, xl);
    // 2. Weight conversion (bf16 hi/lo)
    convert_w<<<(QC * NC + 255) / 256, 256>>>(qkv_w, qwh, qwl, QC * NC);
    convert_w<<<(NC * NC + 255) / 256, 256>>>(proj_w, pwh, pwl, NC * NC);
    // 3. QKV GEMM v6 (experiment: 256 thr, 16 warps/SM)
    qkv_gemm6<<<dim3(NHW / 64, QC / 128, NB), 256, G6_SMEM>>>(
        qwh, qwl, xh, xl, qkv_b, qkvh, qkvl);
    // 4. Flash attention (mma.sync)
    attn_mma<<<dim3(NHW / 128, NHEADS, NB), 256, ATTN_SMEM>>>();
    // 5. Proj GEMM v3 (control) + bias + residual
    proj_gemm3<<<dim3(NHW / 128, NC / 128, NB), 128, G3_SMEM>>>(
        pwh, pwl, aoh, aol, proj_b, x, out);
}

// round 12
// speedup vs baseline: 1.0672x; 1.0672x over previous
#include <cuda_runtime.h>
#include <cuda_bf16.h>
#include <cuda_fp16.h>
#include <cstdint>
#include <math.h>

// Problem constants
#define NB     16
#define NC     512
#define NHW    1024
#define NHEADS 8
#define ND     64
#define QC     1536     // 3*NC
#define GN_EPS 1e-5f

// ===========================================================================
// Warp-level MMA helpers (sm_80+ paths — legal on base sm_100)
// ===========================================================================
__device__ __forceinline__ uint32_t smem_to_u32(const void* p) {
    uint32_t a;
    asm("{ .reg .u64 t; cvta.to.shared.u64 t, %1; cvt.u32.u64 %0, t; }" : "=r"(a) : "l"(p));
    return a;
}
__device__ __forceinline__ void ldsm4(uint32_t* r, uint32_t addr) {
    asm volatile("ldmatrix.sync.aligned.m8n8.x4.shared.b16 {%0,%1,%2,%3}, [%4];"
                 : "=r"(r[0]), "=r"(r[1]), "=r"(r[2]), "=r"(r[3]) : "r"(addr));
}
__device__ __forceinline__ void ldsm4t(uint32_t* r, uint32_t addr) {
    asm volatile("ldmatrix.sync.aligned.m8n8.x4.trans.shared.b16 {%0,%1,%2,%3}, [%4];"
                 : "=r"(r[0]), "=r"(r[1]), "=r"(r[2]), "=r"(r[3]) : "r"(addr));
}
__device__ __forceinline__ void mma_bf16(float* d, const uint32_t* a, const uint32_t* b) {
    asm volatile("mma.sync.aligned.m16n8k16.row.col.f32.bf16.bf16.f32 "
                 "{%0,%1,%2,%3}, {%4,%5,%6,%7}, {%8,%9}, {%0,%1,%2,%3};"
                 : "+f"(d[0]), "+f"(d[1]), "+f"(d[2]), "+f"(d[3])
                 : "r"(a[0]), "r"(a[1]), "r"(a[2]), "r"(a[3]), "r"(b[0]), "r"(b[1]));
}
__device__ __forceinline__ void mma_fp16(float* d, const uint32_t* a, const uint32_t* b) {
    asm volatile("mma.sync.aligned.m16n8k16.row.col.f32.f16.f16.f32 "
                 "{%0,%1,%2,%3}, {%4,%5,%6,%7}, {%8,%9}, {%0,%1,%2,%3};"
                 : "+f"(d[0]), "+f"(d[1]), "+f"(d[2]), "+f"(d[3])
                 : "r"(a[0]), "r"(a[1]), "r"(a[2]), "r"(a[3]), "r"(b[0]), "r"(b[1]));
}
__device__ __forceinline__ void mma4(float* d, uint32_t a0, uint32_t a1, uint32_t a2,
                                     uint32_t a3, uint32_t b0, uint32_t b1) {
    asm volatile("mma.sync.aligned.m16n8k16.row.col.f32.bf16.bf16.f32 "
                 "{%0,%1,%2,%3}, {%4,%5,%6,%7}, {%8,%9}, {%0,%1,%2,%3};"
                 : "+f"(d[0]), "+f"(d[1]), "+f"(d[2]), "+f"(d[3])
                 : "r"(a0), "r"(a1), "r"(a2), "r"(a3), "r"(b0), "r"(b1));
}
__device__ __forceinline__ void cp_async16(uint32_t daddr, const void* g) {
    asm volatile("cp.async.cg.shared.global [%0], [%1], 16;" :: "r"(daddr), "l"(g));
}
#define CP_COMMIT() asm volatile("cp.async.commit_group;" ::: "memory")
#define CP_WAIT(N)  asm volatile("cp.async.wait_group %0;" :: "n"(N) : "memory")

// pack two fp32 -> bf16x2 (element0 in low half)
__device__ __forceinline__ uint32_t packbf(float lo, float hi) {
    uint32_t r;
    asm("cvt.rn.bf16x2.f32 %0, %1, %2;" : "=r"(r) : "f"(hi), "f"(lo));
    return r;
}
// pack two fp32 -> f16x2 (element0 in low half)
__device__ __forceinline__ uint32_t packhf(float lo, float hi) {
    uint32_t r;
    asm("cvt.rn.f16x2.f32 %0, %1, %2;" : "=r"(r) : "f"(hi), "f"(lo));
    return r;
}

// ===========================================================================
// Scratch (device globals — no allocation allowed)
// ===========================================================================
__device__ __nv_bfloat16 g_xh [NB * NHW * NC];       // gn out hi [b][n][c]
__device__ __nv_bfloat16 g_xl [NB * NHW * NC];       // gn out lo
__device__ __half        g_aoh[NB * NHW * NC];       // attn out hi fp16 [b][n][c]
__device__ __half        g_aol[NB * NHW * NC];       // attn out lo fp16
__device__ __nv_bfloat16 g_qkvh[NB * QC * NHW];      // qkv hi [b][o][n] (Q pre-scaled)
__device__ __nv_bfloat16 g_qkvl[NB * QC * NHW];      // qkv lo
__device__ __nv_bfloat16 g_qwh[QC * NC];             // qkv_w hi  [o][c]
__device__ __nv_bfloat16 g_qwl[QC * NC];
__device__ __half        g_pwh[NC * NC];             // proj_w fp16 [o][c]

// ---------------------------------------------------------------------------
// Kernel 1: GroupNorm fused with transpose+bf16 hi/lo convert.
// ---------------------------------------------------------------------------
__global__ __launch_bounds__(512) void gn_convert(const float* __restrict__ x,
                                                  const float* __restrict__ gw,
                                                  const float* __restrict__ gb,
                                                  __nv_bfloat16* __restrict__ dh,
                                                  __nv_bfloat16* __restrict__ dl) {
    int bg = blockIdx.x;
    int b = bg >> 3, g = bg & 7;
    const float* xp = x + (size_t)(b * NC + g * 64) * NHW;
    const int NE4 = 64 * NHW / 4;
    int tid = threadIdx.x;

    float s = 0.f, s2 = 0.f;
    const float4* xp4 = (const float4*)xp;
    for (int i = tid; i < NE4; i += 512) {
        float4 v = xp4[i];
        s  += v.x + v.y + v.z + v.w;
        s2 += v.x * v.x + v.y * v.y + v.z * v.z + v.w * v.w;
    }
    __shared__ float rs[16], rs2[16];
    #pragma unroll
    for (int o = 16; o > 0; o >>= 1) {
        s  += __shfl_down_sync(0xFFFFFFFFu, s, o);
        s2 += __shfl_down_sync(0xFFFFFFFFu, s2, o);
    }
    int w = tid >> 5, l = tid & 31;
    if (l == 0) { rs[w] = s; rs2[w] = s2; }
    __syncthreads();
    __shared__ float sh_mean, sh_rstd;
    if (tid == 0) {
        float S = 0.f, S2 = 0.f;
        #pragma unroll
        for (int i = 0; i < 16; i++) { S += rs[i]; S2 += rs2[i]; }
        float mean = S * (1.f / 65536.f);
        float var  = S2 * (1.f / 65536.f) - mean * mean;
        sh_mean = mean;
        sh_rstd = rsqrtf(var + GN_EPS);
    }
    __syncthreads();
    float mean = sh_mean, rstd = sh_rstd;

    __shared__ float t[64][33];
    int tcol = tid & 31, trow = tid >> 5;
    int n_l  = tid >> 4;
    int cseg = (tid & 15) * 4;
    float sc[4], bi[4];
    #pragma unroll
    for (int i = 0; i < 4; i++) {
        int c = g * 64 + cseg + i;
        sc[i] = gw[c] * rstd;
        bi[i] = gb[c] - mean * sc[i];
    }

    for (int n0 = 0; n0 < NHW; n0 += 32) {
        __syncthreads();
        #pragma unroll
        for (int i = 0; i < 4; i++) {
            int c = trow + i * 16;
            t[c][tcol] = xp[(size_t)c * NHW + n0 + tcol];
        }
        __syncthreads();
        float f0 = t[cseg + 0][n_l] * sc[0] + bi[0];
        float f1 = t[cseg + 1][n_l] * sc[1] + bi[1];
        float f2 = t[cseg + 2][n_l] * sc[2] + bi[2];
        float f3 = t[cseg + 3][n_l] * sc[3] + bi[3];
        uint32_t h0 = packbf(f0, f1), h1 = packbf(f2, f3);
        uint32_t l0 = packbf(f0 - __uint_as_float(h0 << 16),
                             f1 - __uint_as_float(h0 & 0xFFFF0000u));
        uint32_t l1 = packbf(f2 - __uint_as_float(h1 << 16),
                             f3 - __uint_as_float(h1 & 0xFFFF0000u));
        size_t ob = ((size_t)b * NHW + n0 + n_l) * NC + g * 64 + cseg;
        *(uint2*)(dh + ob) = make_uint2(h0, h1);
        *(uint2*)(dl + ob) = make_uint2(l0, l1);
    }
}

// ---------------------------------------------------------------------------
// Convert weights fp32 -> bf16 hi/lo (qkv) and fp32 -> fp16 (proj)
// ---------------------------------------------------------------------------
__global__ void convert_w(const float* __restrict__ src, __nv_bfloat16* __restrict__ dh,
                          __nv_bfloat16* __restrict__ dl, int n) {
    int i = blockIdx.x * 256 + threadIdx.x;
    if (i < n) {
        float v = src[i];
        __nv_bfloat16 h = __float2bfloat16(v);
        dh[i] = h;
        dl[i] = __float2bfloat16(v - __bfloat162float(h));
    }
}
__global__ void convert_wh(const float* __restrict__ src, __half* __restrict__ dh, int n) {
    int i = blockIdx.x * 256 + threadIdx.x;
    if (i < n) dh[i] = __float2half(src[i]);
}

// ---------------------------------------------------------------------------
// QKV GEMM v5 (R10 proven): CTA 128(o) x 64(n), 4 warps (2x2), warp 64x32.
// bf16x3 split, k-chunk 64, 144B rows, 2-stage, 108KB smem -> 2 CTAs/SM.
// ---------------------------------------------------------------------------
#define G5_ROW    144
#define G5_A_TILE (128 * G5_ROW)            // 18432
#define G5_B_TILE (64 * G5_ROW)             // 9216
#define G5_STAGE  (2 * G5_A_TILE + 2 * G5_B_TILE)   // 55296
#define G5_SMEM   (2 * G5_STAGE)                    // 110592

__global__ __launch_bounds__(128, 2) void qkv_gemm5(
        const __nv_bfloat16* __restrict__ Ah, const __nv_bfloat16* __restrict__ Al,
        const __nv_bfloat16* __restrict__ Bh, const __nv_bfloat16* __restrict__ Bl,
        const float* __restrict__ bias,
        __nv_bfloat16* __restrict__ outh, __nv_bfloat16* __restrict__ outl) {
    extern __shared__ char smem[];
    uint32_t smem_u = smem_to_u32(smem);
    int tid = threadIdx.x;
    int warp = tid >> 5, lane = tid & 31;
    int wm = warp & 1, wn = warp >> 1;      // 2(o) x 2(n)
    int n0 = blockIdx.x * 64;
    int o0 = blockIdx.y * 128;
    int b  = blockIdx.z;

    const __nv_bfloat16* a0 = Ah + (size_t)o0 * NC;
    const __nv_bfloat16* a1 = Al + (size_t)o0 * NC;
    const __nv_bfloat16* b0 = Bh + ((size_t)b * NHW + n0) * NC;
    const __nv_bfloat16* b1 = Bl + ((size_t)b * NHW + n0) * NC;

    auto load_stage = [&](int chunk, int s) {
        int k0 = chunk * 64;
        uint32_t sbase = smem_u + s * G5_STAGE;
        #pragma unroll
        for (int t = 0; t < 16; t++) {       // A hi/lo: 2048 cp
            int idx = t * 128 + tid;
            int tile = idx >> 10;
            int r = (idx >> 3) & 127;
            int ch = idx & 7;
            const __nv_bfloat16* src = tile ? a1 : a0;
            cp_async16(sbase + tile * G5_A_TILE + r * G5_ROW + ch * 16,
                       src + (size_t)r * NC + k0 + ch * 8);
        }
        #pragma unroll
        for (int t = 0; t < 8; t++) {        // B hi/lo: 1024 cp
            int idx = t * 128 + tid;
            int tile = idx >> 9;
            int r = (idx >> 3) & 63;
            int ch = idx & 7;
            const __nv_bfloat16* src = tile ? b1 : b0;
            cp_async16(sbase + 2 * G5_A_TILE + tile * G5_B_TILE + r * G5_ROW + ch * 16,
                       src + (size_t)r * NC + k0 + ch * 8);
        }
        CP_COMMIT();
    };

    float acc[4][4][4] = {};
    uint32_t aLane = (uint32_t)((lane & 15) * G5_ROW + (lane >> 4) * 16);
    uint32_t bLane = (uint32_t)(((lane & 7) + ((lane >> 4) << 3)) * G5_ROW +
                                ((lane >> 3) & 1) * 16);

    load_stage(0, 0);
    #pragma unroll 1
    for (int c = 0; c < 8; c++) {
        if (c + 1 < 8) { load_stage(c + 1, (c + 1) & 1); CP_WAIT(1); }
        else { CP_WAIT(0); }
        __syncthreads();

        uint32_t sb = smem_u + (c & 1) * G5_STAGE;
        uint32_t offAh = sb                 + (wm * 64) * G5_ROW + aLane;
        uint32_t offAl = offAh + G5_A_TILE;
        uint32_t offBh = sb + 2 * G5_A_TILE + (wn * 32) * G5_ROW + bLane;
        uint32_t offBl = offBh + G5_B_TILE;

        #pragma unroll
        for (int ks = 0; ks < 4; ks++) {
            uint32_t ko = ks * 32;
            uint32_t af[4][4], bh[2][4], bl[2][4];
            #pragma unroll
            for (int i = 0; i < 4; i++) ldsm4(af[i], offAh + i * 16 * G5_ROW + ko);
            #pragma unroll
            for (int g = 0; g < 2; g++) ldsm4(bh[g], offBh + g * 16 * G5_ROW + ko);
            #pragma unroll
            for (int g = 0; g < 2; g++) ldsm4(bl[g], offBl + g * 16 * G5_ROW + ko);
            #pragma unroll
            for (int i = 0; i < 4; i++)
                #pragma unroll
                for (int j = 0; j < 4; j++)
                    mma_bf16(acc[i][j], af[i], &bh[j >> 1][(j & 1) * 2]);
            #pragma unroll
            for (int i = 0; i < 4; i++)
                #pragma unroll
                for (int j = 0; j < 4; j++)
                    mma_bf16(acc[i][j], af[i], &bl[j >> 1][(j & 1) * 2]);
            #pragma unroll
            for (int i = 0; i < 4; i++) ldsm4(af[i], offAl + i * 16 * G5_ROW + ko);
            #pragma unroll
            for (int i = 0; i < 4; i++)
                #pragma unroll
                for (int j = 0; j < 4; j++)
                    mma_bf16(acc[i][j], af[i], &bh[j >> 1][(j & 1) * 2]);
        }
        __syncthreads();
    }

    int r0 = lane >> 2, c0 = (lane & 3) * 2;
    #pragma unroll
    for (int i = 0; i < 4; i++) {
        #pragma unroll
        for (int half = 0; half < 2; half++) {
            int o = o0 + wm * 64 + i * 16 + r0 + half * 8;
            float bi = bias[o];
            float scq = (o < NC) ? 0.125f : 1.0f;
            size_t rowb = ((size_t)b * QC + o) * NHW + n0 + wn * 32 + c0;
            #pragma unroll
            for (int j = 0; j < 4; j++) {
                float v0 = (acc[i][j][half * 2]     + bi) * scq;
                float v1 = (acc[i][j][half * 2 + 1] + bi) * scq;
                uint32_t hp = packbf(v0, v1);
                uint32_t lp = packbf(v0 - __uint_as_float(hp << 16),
                                     v1 - __uint_as_float(hp & 0xFFFF0000u));
                *(uint32_t*)(outh + rowb + j * 8) = hp;
                *(uint32_t*)(outl + rowb + j * 8) = lp;
            }
        }
    }
}

// ---------------------------------------------------------------------------
// Proj GEMM fp16 2-pass: D = Wh*(Xh + Xl), W single fp16 tensor.
// CTA 128(o) x 64(n), 4 warps (2x2) warp 64x32, k-chunk 64, 144B rows,
// 2-stage, 72KB smem -> 2 CTAs/SM. Grid 1024 -> 3.5 waves (tail fix).
// ---------------------------------------------------------------------------
#define PJ_ROW    144
#define PJ_A_TILE (128 * PJ_ROW)            // 18432
#define PJ_B_TILE (64 * PJ_ROW)             // 9216
#define PJ_STAGE  (PJ_A_TILE + 2 * PJ_B_TILE)       // 36864
#define PJ_SMEM   (2 * PJ_STAGE)                    // 73728

__global__ __launch_bounds__(128, 2) void proj_fp16(
        const __half* __restrict__ W,
        const __half* __restrict__ Bh, const __half* __restrict__ Bl,
        const float* __restrict__ bias, const float* __restrict__ residual,
        float* __restrict__ out) {
    extern __shared__ char smem[];
    uint32_t smem_u = smem_to_u32(smem);
    int tid = threadIdx.x;
    int warp = tid >> 5, lane = tid & 31;
    int wm = warp & 1, wn = warp >> 1;      // 2(o) x 2(n)
    int n0 = blockIdx.x * 64;
    int o0 = blockIdx.y * 128;
    int b  = blockIdx.z;

    const __half* a0 = W + (size_t)o0 * NC;
    const __half* b0 = Bh + ((size_t)b * NHW + n0) * NC;
    const __half* b1 = Bl + ((size_t)b * NHW + n0) * NC;

    auto load_stage = [&](int chunk, int s) {
        int k0 = chunk * 64;
        uint32_t sbase = smem_u + s * PJ_STAGE;
        #pragma unroll
        for (int t = 0; t < 8; t++) {        // A: 1024 cp
            int idx = t * 128 + tid;
            int r = idx >> 3;
            int ch = idx & 7;
            cp_async16(sbase + r * PJ_ROW + ch * 16,
                       a0 + (size_t)r * NC + k0 + ch * 8);
        }
        #pragma unroll
        for (int t = 0; t < 8; t++) {        // B hi/lo: 1024 cp
            int idx = t * 128 + tid;
            int tile = idx >> 9;
            int r = (idx >> 3) & 63;
            int ch = idx & 7;
            const __half* src = tile ? b1 : b0;
            cp_async16(sbase + PJ_A_TILE + tile * PJ_B_TILE + r * PJ_ROW + ch * 16,
                       src + (size_t)r * NC + k0 + ch * 8);
        }
        CP_COMMIT();
    };

    float acc[4][4][4] = {};
    uint32_t aLane = (uint32_t)((lane & 15) * PJ_ROW + (lane >> 4) * 16);
    uint32_t bLane = (uint32_t)(((lane & 7) + ((lane >> 4) << 3)) * PJ_ROW +
                                ((lane >> 3) & 1) * 16);

    load_stage(0, 0);
    #pragma unroll 1
    for (int c = 0; c < 8; c++) {
        if (c + 1 < 8) { load_stage(c + 1, (c + 1) & 1); CP_WAIT(1); }
        else { CP_WAIT(0); }
        __syncthreads();

        uint32_t sb = smem_u + (c & 1) * PJ_STAGE;
        uint32_t offA  = sb + (wm * 64) * PJ_ROW + aLane;
        uint32_t offBh = sb + PJ_A_TILE + (wn * 32) * PJ_ROW + bLane;
        uint32_t offBl = offBh + PJ_B_TILE;

        #pragma unroll
        for (int ks = 0; ks < 4; ks++) {
            uint32_t ko = ks * 32;
            uint32_t af[4][4], bh[2][4], bl[2][4];
            #pragma unroll
            for (int i = 0; i < 4; i++) ldsm4(af[i], offA + i * 16 * PJ_ROW + ko);
            #pragma unroll
            for (int g = 0; g < 2; g++) ldsm4(bh[g], offBh + g * 16 * PJ_ROW + ko);
            #pragma unroll
            for (int g = 0; g < 2; g++) ldsm4(bl[g], offBl + g * 16 * PJ_ROW + ko);
            #pragma unroll
            for (int i = 0; i < 4; i++)
                #pragma unroll
                for (int j = 0; j < 4; j++)
                    mma_fp16(acc[i][j], af[i], &bh[j >> 1][(j & 1) * 2]);
            #pragma unroll
            for (int i = 0; i < 4; i++)
                #pragma unroll
                for (int j = 0; j < 4; j++)
                    mma_fp16(acc[i][j], af[i], &bl[j >> 1][(j & 1) * 2]);
        }
        __syncthreads();
    }

    int r0 = lane >> 2, c0 = (lane & 3) * 2;
    #pragma unroll
    for (int i = 0; i < 4; i++) {
        #pragma unroll
        for (int half = 0; half < 2; half++) {
            int o = o0 + wm * 64 + i * 16 + r0 + half * 8;
            float bi = bias[o];
            size_t rowb = ((size_t)b * NC + o) * NHW + n0 + wn * 32 + c0;
            #pragma unroll
            for (int j = 0; j < 4; j++) {
                float v0 = acc[i][j][half * 2]     + bi;
                float v1 = acc[i][j][half * 2 + 1] + bi;
                size_t off = rowb + j * 8;
                float2 rr = *(const float2*)&residual[off];
                *(float2*)&out[off] = make_float2(v0 + rr.x, v1 + rr.y);
            }
        }
    }
}

// ---------------------------------------------------------------------------
// Flash attention via mma.sync, bf16x3 split. Epilogue now writes fp16 hi/lo.
// ---------------------------------------------------------------------------
#define QSTR 136
#define KSTR 72
#define OSTR 132
#define Q_BYTES   17408
#define KV_TILE_B 9216
#define STAGE0_OFF (2 * Q_BYTES)
#define KV_STAGE_B (4 * KV_TILE_B)
#define ATTN_SMEM (STAGE0_OFF + 2 * KV_STAGE_B)

__global__ __launch_bounds__(256, 2) void attn_mma() {
    extern __shared__ char smem[];
    uint32_t smem_u = smem_to_u32(smem);
    int tid  = threadIdx.x;
    int warp = tid >> 5, lane = tid & 31;
    int wbase = warp * 16;
    int qt = blockIdx.x, h = blockIdx.y, b = blockIdx.z;

    const __nv_bfloat16* gq_h = g_qkvh + ((size_t)b * QC + h * ND) * NHW;
    const __nv_bfloat16* gq_l = g_qkvl + ((size_t)b * QC + h * ND) * NHW;
    const __nv_bfloat16* gk_h = g_qkvh + ((size_t)b * QC + NC + h * ND) * NHW;
    const __nv_bfloat16* gk_l = g_qkvl + ((size_t)b * QC + NC + h * ND) * NHW;
    const __nv_bfloat16* gv_h = g_qkvh + ((size_t)b * QC + 2 * NC + h * ND) * NHW;
    const __nv_bfloat16* gv_l = g_qkvl + ((size_t)b * QC + 2 * NC + h * ND) * NHW;
    const __nv_bfloat16* kvsrc[4] = {gk_h, gk_l, gv_h, gv_l};

    int rowoff = ((lane >> 4) << 3) + (lane & 7);
    int coloff = ((lane >> 3) & 1) * 8;

    auto load_stage = [&](int kt, int s) {
        uint32_t sb = smem_u + STAGE0_OFF + s * KV_STAGE_B;
        #pragma unroll
        for (int k = 0; k < 8; k++) {
            int c = tid + k * 256;
            int tile = c >> 9, row = (c >> 3) & 63, ch = c & 7;
            cp_async16(sb + tile * KV_TILE_B + row * (KSTR * 2) + ch * 16,
                       kvsrc[tile] + (size_t)row * NHW + kt * 64 + ch * 8);
        }
        CP_COMMIT();
    };

    {
        #pragma unroll
        for (int k = 0; k < 8; k++) {
            int c = tid + k * 256;
            int tile = c >> 10, row = (c >> 4) & 63, ch = c & 15;
            const __nv_bfloat16* src = tile ? gq_l : gq_h;
            cp_async16(smem_u + tile * Q_BYTES + row * (QSTR * 2) + ch * 16,
                       src + (size_t)row * NHW + qt * 128 + ch * 8);
        }
    }
    load_stage(0, 0);

    float m0 = -1e30f, m1 = -1e30f, l0 = 0.f, l1 = 0.f;
    float oacc[8][4] = {};

    uint32_t qAddrH = smem_u + (uint32_t)(rowoff * (QSTR * 2) + (wbase + coloff) * 2);
    uint32_t qAddrL = qAddrH + Q_BYTES;

    #pragma unroll 1
    for (int kt = 0; kt < 16; kt++) {
        CP_WAIT(0);
        __syncthreads();
        if (kt < 15) load_stage(kt + 1, (kt + 1) & 1);

        uint32_t sb = smem_u + STAGE0_OFF + (kt & 1) * KV_STAGE_B;
        float sacc[8][4] = {};
        #pragma unroll
        for (int kc = 0; kc < 4; kc++) {
            uint32_t qh[4], ql[4];
            ldsm4t(qh, qAddrH + kc * 16 * (QSTR * 2));
            ldsm4t(ql, qAddrL + kc * 16 * (QSTR * 2));
            uint32_t kBase = sb + (uint32_t)((kc * 16 + rowoff) * (KSTR * 2) + coloff * 2);
            #pragma unroll
            for (int ko2 = 0; ko2 < 4; ko2++) {
                uint32_t kh[4], kl[4];
                ldsm4t(kh, kBase + ko2 * 32);
                ldsm4t(kl, kBase + KV_TILE_B + ko2 * 32);
                mma4(sacc[2*ko2],   qh[0],qh[1],qh[2],qh[3], kh[0], kh[2]);
                mma4(sacc[2*ko2+1], qh[0],qh[1],qh[2],qh[3], kh[1], kh[3]);
                mma4(sacc[2*ko2],   qh[0],qh[1],qh[2],qh[3], kl[0], kl[2]);
                mma4(sacc[2*ko2+1], qh[0],qh[1],qh[2],qh[3], kl[1], kl[3]);
                mma4(sacc[2*ko2],   ql[0],ql[1],ql[2],ql[3], kh[0], kh[2]);
                mma4(sacc[2*ko2+1], ql[0],ql[1],ql[2],ql[3], kh[1], kh[3]);
            }
        }

        float tm0 = -1e30f, tm1 = -1e30f;
        #pragma unroll
        for (int j = 0; j < 8; j++) {
            tm0 = fmaxf(tm0, fmaxf(sacc[j][0], sacc[j][1]));
            tm1 = fmaxf(tm1, fmaxf(sacc[j][2], sacc[j][3]));
        }
        tm0 = fmaxf(tm0, __shfl_xor_sync(0xFFFFFFFFu, tm0, 1));
        tm0 = fmaxf(tm0, __shfl_xor_sync(0xFFFFFFFFu, tm0, 2));
        tm1 = fmaxf(tm1, __shfl_xor_sync(0xFFFFFFFFu, tm1, 1));
        tm1 = fmaxf(tm1, __shfl_xor_sync(0xFFFFFFFFu, tm1, 2));
        float nm0 = fmaxf(m0, tm0), nm1 = fmaxf(m1, tm1);
        float al0 = __expf(m0 - nm0), al1 = __expf(m1 - nm1);
        m0 = nm0; m1 = nm1;
        float sum0 = 0.f, sum1 = 0.f;
        #pragma unroll
        for (int j = 0; j < 8; j++) {
            sacc[j][0] = __expf(sacc[j][0] - m0); sum0 += sacc[j][0];
            sacc[j][1] = __expf(sacc[j][1] - m0); sum0 += sacc[j][1];
            sacc[j][2] = __expf(sacc[j][2] - m1); sum1 += sacc[j][2];
            sacc[j][3] = __expf(sacc[j][3] - m1); sum1 += sacc[j][3];
        }
        sum0 += __shfl_xor_sync(0xFFFFFFFFu, sum0, 1);
        sum0 += __shfl_xor_sync(0xFFFFFFFFu, sum0, 2);
        sum1 += __shfl_xor_sync(0xFFFFFFFFu, sum1, 1);
        sum1 += __shfl_xor_sync(0xFFFFFFFFu, sum1, 2);
        l0 = l0 * al0 + sum0;
        l1 = l1 * al1 + sum1;
        #pragma unroll
        for (int d = 0; d < 8; d++) {
            oacc[d][0] *= al0; oacc[d][1] *= al0;
            oacc[d][2] *= al1; oacc[d][3] *= al1;
        }

        uint32_t vB = sb + 2 * KV_TILE_B;
        #pragma unroll
        for (int kc2 = 0; kc2 < 4; kc2++) {
            int j0 = 2 * kc2, j1 = j0 + 1;
            uint32_t pa0 = packbf(sacc[j0][0], sacc[j0][1]);
            uint32_t pa1 = packbf(sacc[j0][2], sacc[j0][3]);
            uint32_t pa2 = packbf(sacc[j1][0], sacc[j1][1]);
            uint32_t pa3 = packbf(sacc[j1][2], sacc[j1][3]);
            uint32_t pl0 = packbf(sacc[j0][0] - __uint_as_float(pa0 << 16),
                                  sacc[j0][1] - __uint_as_float(pa0 & 0xFFFF0000u));
            uint32_t pl1 = packbf(sacc[j0][2] - __uint_as_float(pa1 << 16),
                                  sacc[j0][3] - __uint_as_float(pa1 & 0xFFFF0000u));
            uint32_t pl2 = packbf(sacc[j1][0] - __uint_as_float(pa2 << 16),
                                  sacc[j1][1] - __uint_as_float(pa2 & 0xFFFF0000u));
            uint32_t pl3 = packbf(sacc[j1][2] - __uint_as_float(pa3 << 16),
                                  sacc[j1][3] - __uint_as_float(pa3 & 0xFFFF0000u));
            uint32_t vCol = (uint32_t)((kc2 * 16 + coloff) * 2);
            #pragma unroll
            for (int do2 = 0; do2 < 4; do2++) {
                uint32_t vh[4], vl[4];
                uint32_t vRow = (uint32_t)((do2 * 16 + rowoff) * (KSTR * 2));
                ldsm4(vh, vB + vRow + vCol);
                ldsm4(vl, vB + KV_TILE_B + vRow + vCol);
                mma4(oacc[2*do2],   pa0,pa1,pa2,pa3, vh[0], vh[1]);
                mma4(oacc[2*do2+1], pa0,pa1,pa2,pa3, vh[2], vh[3]);
                mma4(oacc[2*do2],   pl0,pl1,pl2,pl3, vh[0], vh[1]);
                mma4(oacc[2*do2+1], pl0,pl1,pl2,pl3, vh[2], vh[3]);
                mma4(oacc[2*do2],   pa0,pa1,pa2,pa3, vl[0], vl[1]);
                mma4(oacc[2*do2+1], pa0,pa1,pa2,pa3, vl[2], vl[3]);
            }
        }
    }

    float* Os = (float*)(smem + STAGE0_OFF);
    float linv0 = 1.f / l0, linv1 = 1.f / l1;
    int r0q = wbase + (lane >> 2);
    int ddc = (lane & 3) * 2;
    #pragma unroll
    for (int d = 0; d < 8; d++) {
        Os[(d * 8 + ddc)     * OSTR + r0q]     = oacc[d][0] * linv0;
        Os[(d * 8 + ddc + 1) * OSTR + r0q]     = oacc[d][1] * linv0;
        Os[(d * 8 + ddc)     * OSTR + r0q + 8] = oacc[d][2] * linv1;
        Os[(d * 8 + ddc + 1) * OSTR + r0q + 8] = oacc[d][3] * linv1;
    }
    __syncthreads();

    // coop write: fp16 hi/lo to [b][n][c]
    {
        int q = tid >> 1;
        int ddb = (tid & 1) * 32;
        uint32_t hb[16], lb[16];
        #pragma unroll
        for (int d = 0; d < 32; d += 2) {
            float f0 = Os[(ddb + d)     * OSTR + q];
            float f1 = Os[(ddb + d + 1) * OSTR + q];
            uint32_t hp = packhf(f0, f1);
            __half2 hv = *(__half2*)&hp;
            float r0f = f0 - __half2float(hv.x);
            float r1f = f1 - __half2float(hv.y);
            hb[d >> 1] = hp;
            lb[d >> 1] = packhf(r0f, r1f);
        }
        size_t base = ((size_t)b * NHW + qt * 128 + q) * NC + h * 64 + ddb;
        #pragma unroll
        for (int u = 0; u < 4; u++) {
            *(uint4*)(g_aoh + base + u * 8) = *(uint4*)&hb[u * 4];
            *(uint4*)(g_aol + base + u * 8) = *(uint4*)&lb[u * 4];
        }
    }
}

// ---------------------------------------------------------------------------
extern "C" void kernel_launch(void* const* d_in, const int* in_sizes, int n_in,
                              void* d_out, int out_size) {
    const float* x      = (const float*)d_in[0];
    const float* gn_w   = (const float*)d_in[1];
    const float* gn_b   = (const float*)d_in[2];
    const float* qkv_w  = (const float*)d_in[3];
    const float* qkv_b  = (const float*)d_in[4];
    const float* proj_w = (const float*)d_in[5];
    const float* proj_b = (const float*)d_in[6];
    float* out = (float*)d_out;

    cudaFuncSetAttribute(qkv_gemm5, cudaFuncAttributeMaxDynamicSharedMemorySize, G5_SMEM);
    cudaFuncSetAttribute(proj_fp16, cudaFuncAttributeMaxDynamicSharedMemorySize, PJ_SMEM);
    cudaFuncSetAttribute(attn_mma, cudaFuncAttributeMaxDynamicSharedMemorySize, ATTN_SMEM);

    __nv_bfloat16 *qwh, *qwl, *xh, *xl, *qkvh, *qkvl;
    __half *pwh, *aoh, *aol;
    cudaGetSymbolAddress((void**)&qwh, g_qwh);
    cudaGetSymbolAddress((void**)&qwl, g_qwl);
    cudaGetSymbolAddress((void**)&pwh, g_pwh);
    cudaGetSymbolAddress((void**)&xh,  g_xh);
    cudaGetSymbolAddress((void**)&xl,  g_xl);
    cudaGetSymbolAddress((void**)&aoh, g_aoh);
    cudaGetSymbolAddress((void**)&aol, g_aol);
    cudaGetSymbolAddress((void**)&qkvh, g_qkvh);
    cudaGetSymbolAddress((void**)&qkvl, g_qkvl);

    // 1. GroupNorm fused with transpose+bf16 convert -> g_xh/g_xl [b][n][c]
    gn_convert<<<NB * 8, 512>>>(x, gn_w, gn_b, xh, xl);
    // 2. Weight conversion
    convert_w<<<(QC * NC + 255) / 256, 256>>>(qkv_w, qwh, qwl, QC * NC);
    convert_wh<<<(NC * NC + 255) / 256, 256>>>(proj_w, pwh, NC * NC);
    // 3. QKV GEMM (bf16x3, R10-proven), writes bf16 hi/lo (Q scaled)
    qkv_gemm5<<<dim3(NHW / 64, QC / 128, NB), 128, G5_SMEM>>>(
        qwh, qwl, xh, xl, qkv_b, qkvh, qkvl);
    // 4. Flash attention, writes fp16 hi/lo ao [b][n][c]
    attn_mma<<<dim3(NHW / 128, NHEADS, NB), 256, ATTN_SMEM>>>();
    // 5. Proj GEMM fp16 2-pass + bias + residual
    proj_fp16<<<dim3(NHW / 64, NC / 128, NB), 128, PJ_SMEM>>>(
        pwh, aoh, aol, proj_b, x, out);
}

// round 14
// speedup vs baseline: 1.4693x; 1.3767x over previous
#include <cuda_runtime.h>
#include <cuda_bf16.h>
#include <cuda_fp16.h>
#include <cstdint>
#include <math.h>

// Problem constants
#define NB     16
#define NC     512
#define NHW    1024
#define NHEADS 8
#define ND     64
#define QC     1536     // 3*NC
#define GN_EPS 1e-5f

// ===========================================================================
// Warp-level MMA helpers (sm_80+ paths — legal on base sm_100)
// ===========================================================================
__device__ __forceinline__ uint32_t smem_to_u32(const void* p) {
    uint32_t a;
    asm("{ .reg .u64 t; cvta.to.shared.u64 t, %1; cvt.u32.u64 %0, t; }" : "=r"(a) : "l"(p));
    return a;
}
__device__ __forceinline__ void ldsm4(uint32_t* r, uint32_t addr) {
    asm volatile("ldmatrix.sync.aligned.m8n8.x4.shared.b16 {%0,%1,%2,%3}, [%4];"
                 : "=r"(r[0]), "=r"(r[1]), "=r"(r[2]), "=r"(r[3]) : "r"(addr));
}
__device__ __forceinline__ void ldsm4t(uint32_t* r, uint32_t addr) {
    asm volatile("ldmatrix.sync.aligned.m8n8.x4.trans.shared.b16 {%0,%1,%2,%3}, [%4];"
                 : "=r"(r[0]), "=r"(r[1]), "=r"(r[2]), "=r"(r[3]) : "r"(addr));
}
__device__ __forceinline__ void mma_fp16(float* d, const uint32_t* a, const uint32_t* b) {
    asm volatile("mma.sync.aligned.m16n8k16.row.col.f32.f16.f16.f32 "
                 "{%0,%1,%2,%3}, {%4,%5,%6,%7}, {%8,%9}, {%0,%1,%2,%3};"
                 : "+f"(d[0]), "+f"(d[1]), "+f"(d[2]), "+f"(d[3])
                 : "r"(a[0]), "r"(a[1]), "r"(a[2]), "r"(a[3]), "r"(b[0]), "r"(b[1]));
}
__device__ __forceinline__ void mma4h(float* d, uint32_t a0, uint32_t a1, uint32_t a2,
                                      uint32_t a3, uint32_t b0, uint32_t b1) {
    asm volatile("mma.sync.aligned.m16n8k16.row.col.f32.f16.f16.f32 "
                 "{%0,%1,%2,%3}, {%4,%5,%6,%7}, {%8,%9}, {%0,%1,%2,%3};"
                 : "+f"(d[0]), "+f"(d[1]), "+f"(d[2]), "+f"(d[3])
                 : "r"(a0), "r"(a1), "r"(a2), "r"(a3), "r"(b0), "r"(b1));
}
__device__ __forceinline__ void cp_async16(uint32_t daddr, const void* g) {
    asm volatile("cp.async.cg.shared.global [%0], [%1], 16;" :: "r"(daddr), "l"(g));
}
#define CP_COMMIT() asm volatile("cp.async.commit_group;" ::: "memory")
#define CP_WAIT(N)  asm volatile("cp.async.wait_group %0;" :: "n"(N) : "memory")

// pack two fp32 -> f16x2 (element0 in low half)
__device__ __forceinline__ uint32_t packhf(float lo, float hi) {
    uint32_t r;
    asm("cvt.rn.f16x2.f32 %0, %1, %2;" : "=r"(r) : "f"(hi), "f"(lo));
    return r;
}
// split two fp32 into fp16 hi + fp16 residual pair
__device__ __forceinline__ uint32_t split_h(float f0, float f1, uint32_t& lo) {
    uint32_t hp = packhf(f0, f1);
    __half2 hv = *(__half2*)&hp;
    lo = packhf(f0 - __half2float(hv.x), f1 - __half2float(hv.y));
    return hp;
}

// ===========================================================================
// Scratch (device globals — no allocation allowed)
// ===========================================================================
__device__ __half g_xh [NB * NHW * NC];       // gn out hi fp16 [b][n][c]
__device__ __half g_xl [NB * NHW * NC];       // gn out lo
__device__ __half g_aoh[NB * NHW * NC];       // attn out hi fp16 [b][n][c]
__device__ __half g_aol[NB * NHW * NC];       // attn out lo
__device__ __half g_qkvh[NB * QC * NHW];      // qkv hi fp16 [b][o][n] (Q pre-scaled)
__device__ __half g_qkvl[NB * QC * NHW];      // qkv lo
__device__ __half g_qwh[QC * NC];             // qkv_w fp16 [o][c]
__device__ __half g_pwh[NC * NC];             // proj_w fp16 [o][c]

// ---------------------------------------------------------------------------
// Kernel 1: GroupNorm fused with transpose+fp16 hi/lo convert.
// ---------------------------------------------------------------------------
__global__ __launch_bounds__(512) void gn_convert(const float* __restrict__ x,
                                                  const float* __restrict__ gw,
                                                  const float* __restrict__ gb,
                                                  __half* __restrict__ dh,
                                                  __half* __restrict__ dl) {
    int bg = blockIdx.x;
    int b = bg >> 3, g = bg & 7;
    const float* xp = x + (size_t)(b * NC + g * 64) * NHW;
    const int NE4 = 64 * NHW / 4;
    int tid = threadIdx.x;

    float s = 0.f, s2 = 0.f;
    const float4* xp4 = (const float4*)xp;
    for (int i = tid; i < NE4; i += 512) {
        float4 v = xp4[i];
        s  += v.x + v.y + v.z + v.w;
        s2 += v.x * v.x + v.y * v.y + v.z * v.z + v.w * v.w;
    }
    __shared__ float rs[16], rs2[16];
    #pragma unroll
    for (int o = 16; o > 0; o >>= 1) {
        s  += __shfl_down_sync(0xFFFFFFFFu, s, o);
        s2 += __shfl_down_sync(0xFFFFFFFFu, s2, o);
    }
    int w = tid >> 5, l = tid & 31;
    if (l == 0) { rs[w] = s; rs2[w] = s2; }
    __syncthreads();
    __shared__ float sh_mean, sh_rstd;
    if (tid == 0) {
        float S = 0.f, S2 = 0.f;
        #pragma unroll
        for (int i = 0; i < 16; i++) { S += rs[i]; S2 += rs2[i]; }
        float mean = S * (1.f / 65536.f);
        float var  = S2 * (1.f / 65536.f) - mean * mean;
        sh_mean = mean;
        sh_rstd = rsqrtf(var + GN_EPS);
    }
    __syncthreads();
    float mean = sh_mean, rstd = sh_rstd;

    __shared__ float t[64][33];
    int tcol = tid & 31, trow = tid >> 5;
    int n_l  = tid >> 4;
    int cseg = (tid & 15) * 4;
    float sc[4], bi[4];
    #pragma unroll
    for (int i = 0; i < 4; i++) {
        int c = g * 64 + cseg + i;
        sc[i] = gw[c] * rstd;
        bi[i] = gb[c] - mean * sc[i];
    }

    for (int n0 = 0; n0 < NHW; n0 += 32) {
        __syncthreads();
        #pragma unroll
        for (int i = 0; i < 4; i++) {
            int c = trow + i * 16;
            t[c][tcol] = xp[(size_t)c * NHW + n0 + tcol];
        }
        __syncthreads();
        float f0 = t[cseg + 0][n_l] * sc[0] + bi[0];
        float f1 = t[cseg + 1][n_l] * sc[1] + bi[1];
        float f2 = t[cseg + 2][n_l] * sc[2] + bi[2];
        float f3 = t[cseg + 3][n_l] * sc[3] + bi[3];
        uint32_t l0, l1;
        uint32_t h0 = split_h(f0, f1, l0);
        uint32_t h1 = split_h(f2, f3, l1);
        size_t ob = ((size_t)b * NHW + n0 + n_l) * NC + g * 64 + cseg;
        *(uint2*)(dh + ob) = make_uint2(h0, h1);
        *(uint2*)(dl + ob) = make_uint2(l0, l1);
    }
}

// ---------------------------------------------------------------------------
// Convert weights fp32 -> fp16 (single)
// ---------------------------------------------------------------------------
__global__ void convert_wh(const float* __restrict__ src, __half* __restrict__ dh, int n) {
    int i = blockIdx.x * 256 + threadIdx.x;
    if (i < n) dh[i] = __float2half(src[i]);
}

// ---------------------------------------------------------------------------
// Shared fp16 2-pass GEMM geometry: CTA 128(o) x 64(n), 4 warps (2x2),
// warp 64x32, k-chunk 64, 144B rows, 2-stage, 72KB smem -> 2 CTAs/SM.
// D = W * (Xh + Xl), W single fp16.
// ---------------------------------------------------------------------------
#define PJ_ROW    144
#define PJ_A_TILE (128 * PJ_ROW)            // 18432
#define PJ_B_TILE (64 * PJ_ROW)             // 9216
#define PJ_STAGE  (PJ_A_TILE + 2 * PJ_B_TILE)       // 36864
#define PJ_SMEM   (2 * PJ_STAGE)                    // 73728

#define H2_MAINLOOP()                                                          \
    auto load_stage = [&](int chunk, int s) {                                  \
        int k0 = chunk * 64;                                                   \
        uint32_t sbase = smem_u + s * PJ_STAGE;                                \
        _Pragma("unroll")                                                      \
        for (int t = 0; t < 8; t++) {                                          \
            int idx = t * 128 + tid;                                           \
            int r = idx >> 3;                                                  \
            int ch = idx & 7;                                                  \
            cp_async16(sbase + r * PJ_ROW + ch * 16,                           \
                       a0 + (size_t)r * NC + k0 + ch * 8);                     \
        }                                                                      \
        _Pragma("unroll")                                                      \
        for (int t = 0; t < 8; t++) {                                          \
            int idx = t * 128 + tid;                                           \
            int tile = idx >> 9;                                               \
            int r = (idx >> 3) & 63;                                           \
            int ch = idx & 7;                                                  \
            const __half* src = tile ? b1 : b0;                                \
            cp_async16(sbase + PJ_A_TILE + tile * PJ_B_TILE + r * PJ_ROW +     \
                           ch * 16,                                            \
                       src + (size_t)r * NC + k0 + ch * 8);                    \
        }                                                                      \
        CP_COMMIT();                                                           \
    };                                                                         \
    float acc[4][4][4] = {};                                                   \
    uint32_t aLane = (uint32_t)((lane & 15) * PJ_ROW + (lane >> 4) * 16);      \
    uint32_t bLane = (uint32_t)(((lane & 7) + ((lane >> 4) << 3)) * PJ_ROW +   \
                                ((lane >> 3) & 1) * 16);                       \
    load_stage(0, 0);                                                          \
    _Pragma("unroll 1")                                                        \
    for (int c = 0; c < 8; c++) {                                              \
        if (c + 1 < 8) { load_stage(c + 1, (c + 1) & 1); CP_WAIT(1); }         \
        else { CP_WAIT(0); }                                                   \
        __syncthreads();                                                       \
        uint32_t sb = smem_u + (c & 1) * PJ_STAGE;                             \
        uint32_t offA  = sb + (wm * 64) * PJ_ROW + aLane;                      \
        uint32_t offBh = sb + PJ_A_TILE + (wn * 32) * PJ_ROW + bLane;          \
        uint32_t offBl = offBh + PJ_B_TILE;                                    \
        _Pragma("unroll")                                                      \
        for (int ks = 0; ks < 4; ks++) {                                       \
            uint32_t ko = ks * 32;                                             \
            uint32_t af[4][4], bh[2][4], bl[2][4];                             \
            _Pragma("unroll")                                                  \
            for (int i = 0; i < 4; i++) ldsm4(af[i], offA + i * 16 * PJ_ROW + ko);\
            _Pragma("unroll")                                                  \
            for (int g = 0; g < 2; g++) ldsm4(bh[g], offBh + g * 16 * PJ_ROW + ko);\
            _Pragma("unroll")                                                  \
            for (int g = 0; g < 2; g++) ldsm4(bl[g], offBl + g * 16 * PJ_ROW + ko);\
            _Pragma("unroll")                                                  \
            for (int i = 0; i < 4; i++)                                        \
                _Pragma("unroll")                                              \
                for (int j = 0; j < 4; j++)                                    \
                    mma_fp16(acc[i][j], af[i], &bh[j >> 1][(j & 1) * 2]);      \
            _Pragma("unroll")                                                  \
            for (int i = 0; i < 4; i++)                                        \
                _Pragma("unroll")                                              \
                for (int j = 0; j < 4; j++)                                    \
                    mma_fp16(acc[i][j], af[i], &bl[j >> 1][(j & 1) * 2]);      \
        }                                                                      \
        __syncthreads();                                                       \
    }

// QKV: fp16 2-pass, writes fp16 hi/lo in [b][o][n], Q rows scaled by 0.125
__global__ __launch_bounds__(128, 2) void qkv_fp16(
        const __half* __restrict__ W,
        const __half* __restrict__ Bh, const __half* __restrict__ Bl,
        const float* __restrict__ bias,
        __half* __restrict__ outh, __half* __restrict__ outl) {
    extern __shared__ char smem[];
    uint32_t smem_u = smem_to_u32(smem);
    int tid = threadIdx.x;
    int warp = tid >> 5, lane = tid & 31;
    int wm = warp & 1, wn = warp >> 1;
    int n0 = blockIdx.x * 64;
    int o0 = blockIdx.y * 128;
    int b  = blockIdx.z;

    const __half* a0 = W + (size_t)o0 * NC;
    const __half* b0 = Bh + ((size_t)b * NHW + n0) * NC;
    const __half* b1 = Bl + ((size_t)b * NHW + n0) * NC;

    H2_MAINLOOP();

    int r0 = lane >> 2, c0 = (lane & 3) * 2;
    #pragma unroll
    for (int i = 0; i < 4; i++) {
        #pragma unroll
        for (int half = 0; half < 2; half++) {
            int o = o0 + wm * 64 + i * 16 + r0 + half * 8;
            float bi = bias[o];
            float scq = (o < NC) ? 0.125f : 1.0f;
            size_t rowb = ((size_t)b * QC + o) * NHW + n0 + wn * 32 + c0;
            #pragma unroll
            for (int j = 0; j < 4; j++) {
                float v0 = (acc[i][j][half * 2]     + bi) * scq;
                float v1 = (acc[i][j][half * 2 + 1] + bi) * scq;
                uint32_t lp;
                uint32_t hp = split_h(v0, v1, lp);
                *(uint32_t*)(outh + rowb + j * 8) = hp;
                *(uint32_t*)(outl + rowb + j * 8) = lp;
            }
        }
    }
}

// Proj: fp16 2-pass (R12 proven), fp32 out + bias + residual
__global__ __launch_bounds__(128, 2) void proj_fp16(
        const __half* __restrict__ W,
        const __half* __restrict__ Bh, const __half* __restrict__ Bl,
        const float* __restrict__ bias, const float* __restrict__ residual,
        float* __restrict__ out) {
    extern __shared__ char smem[];
    uint32_t smem_u = smem_to_u32(smem);
    int tid = threadIdx.x;
    int warp = tid >> 5, lane = tid & 31;
    int wm = warp & 1, wn = warp >> 1;
    int n0 = blockIdx.x * 64;
    int o0 = blockIdx.y * 128;
    int b  = blockIdx.z;

    const __half* a0 = W + (size_t)o0 * NC;
    const __half* b0 = Bh + ((size_t)b * NHW + n0) * NC;
    const __half* b1 = Bl + ((size_t)b * NHW + n0) * NC;

    H2_MAINLOOP();

    int r0 = lane >> 2, c0 = (lane & 3) * 2;
    #pragma unroll
    for (int i = 0; i < 4; i++) {
        #pragma unroll
        for (int half = 0; half < 2; half++) {
            int o = o0 + wm * 64 + i * 16 + r0 + half * 8;
            float bi = bias[o];
            size_t rowb = ((size_t)b * NC + o) * NHW + n0 + wn * 32 + c0;
            #pragma unroll
            for (int j = 0; j < 4; j++) {
                float v0 = acc[i][j][half * 2]     + bi;
                float v1 = acc[i][j][half * 2 + 1] + bi;
                size_t off = rowb + j * 8;
                float2 rr = *(const float2*)&residual[off];
                *(float2*)&out[off] = make_float2(v0 + rr.x, v1 + rr.y);
            }
        }
    }
}

// ---------------------------------------------------------------------------
// Flash attention fp16: Q hi/lo (exact), K/V hi only.
// S = (Qh+Ql)·Kh ; O = (Ph+Pl)·Vh. 2/3 the mma count of bf16x3.
// FIX vs R13: __syncthreads() before O-staging (stage-1 overlap race).
// ---------------------------------------------------------------------------
#define QSTR 136
#define KSTR 72
#define OSTR 132
#define Q_BYTES   17408
#define KV_TILE_B 9216
#define STAGE0_OFF (2 * Q_BYTES)
#define KV_STAGE_B (2 * KV_TILE_B)
#define ATTN_SMEM (STAGE0_OFF + 2 * KV_STAGE_B)   // 71680

__global__ __launch_bounds__(256, 2) void attn_mma() {
    extern __shared__ char smem[];
    uint32_t smem_u = smem_to_u32(smem);
    int tid  = threadIdx.x;
    int warp = tid >> 5, lane = tid & 31;
    int wbase = warp * 16;
    int qt = blockIdx.x, h = blockIdx.y, b = blockIdx.z;

    const __half* gq_h = g_qkvh + ((size_t)b * QC + h * ND) * NHW;
    const __half* gq_l = g_qkvl + ((size_t)b * QC + h * ND) * NHW;
    const __half* gk_h = g_qkvh + ((size_t)b * QC + NC + h * ND) * NHW;
    const __half* gv_h = g_qkvh + ((size_t)b * QC + 2 * NC + h * ND) * NHW;
    const __half* kvsrc[2] = {gk_h, gv_h};

    int rowoff = ((lane >> 4) << 3) + (lane & 7);
    int coloff = ((lane >> 3) & 1) * 8;

    auto load_stage = [&](int kt, int s) {
        uint32_t sb = smem_u + STAGE0_OFF + s * KV_STAGE_B;
        #pragma unroll
        for (int k = 0; k < 4; k++) {
            int c = tid + k * 256;
            int tile = c >> 9, row = (c >> 3) & 63, ch = c & 7;
            cp_async16(sb + tile * KV_TILE_B + row * (KSTR * 2) + ch * 16,
                       kvsrc[tile] + (size_t)row * NHW + kt * 64 + ch * 8);
        }
        CP_COMMIT();
    };

    {
        #pragma unroll
        for (int k = 0; k < 8; k++) {
            int c = tid + k * 256;
            int tile = c >> 10, row = (c >> 4) & 63, ch = c & 15;
            const __half* src = tile ? gq_l : gq_h;
            cp_async16(smem_u + tile * Q_BYTES + row * (QSTR * 2) + ch * 16,
                       src + (size_t)row * NHW + qt * 128 + ch * 8);
        }
    }
    load_stage(0, 0);

    float m0 = -1e30f, m1 = -1e30f, l0 = 0.f, l1 = 0.f;
    float oacc[8][4] = {};

    uint32_t qAddrH = smem_u + (uint32_t)(rowoff * (QSTR * 2) + (wbase + coloff) * 2);
    uint32_t qAddrL = qAddrH + Q_BYTES;

    #pragma unroll 1
    for (int kt = 0; kt < 16; kt++) {
        CP_WAIT(0);
        __syncthreads();
        if (kt < 15) load_stage(kt + 1, (kt + 1) & 1);

        uint32_t sb = smem_u + STAGE0_OFF + (kt & 1) * KV_STAGE_B;
        float sacc[8][4] = {};
        #pragma unroll
        for (int kc = 0; kc < 4; kc++) {
            uint32_t qh[4], ql[4];
            ldsm4t(qh, qAddrH + kc * 16 * (QSTR * 2));
            ldsm4t(ql, qAddrL + kc * 16 * (QSTR * 2));
            uint32_t kBase = sb + (uint32_t)((kc * 16 + rowoff) * (KSTR * 2) + coloff * 2);
            #pragma unroll
            for (int ko2 = 0; ko2 < 4; ko2++) {
                uint32_t kh[4];
                ldsm4t(kh, kBase + ko2 * 32);
                mma4h(sacc[2*ko2],   qh[0],qh[1],qh[2],qh[3], kh[0], kh[2]);
                mma4h(sacc[2*ko2+1], qh[0],qh[1],qh[2],qh[3], kh[1], kh[3]);
                mma4h(sacc[2*ko2],   ql[0],ql[1],ql[2],ql[3], kh[0], kh[2]);
                mma4h(sacc[2*ko2+1], ql[0],ql[1],ql[2],ql[3], kh[1], kh[3]);
            }
        }

        float tm0 = -1e30f, tm1 = -1e30f;
        #pragma unroll
        for (int j = 0; j < 8; j++) {
            tm0 = fmaxf(tm0, fmaxf(sacc[j][0], sacc[j][1]));
            tm1 = fmaxf(tm1, fmaxf(sacc[j][2], sacc[j][3]));
        }
        tm0 = fmaxf(tm0, __shfl_xor_sync(0xFFFFFFFFu, tm0, 1));
        tm0 = fmaxf(tm0, __shfl_xor_sync(0xFFFFFFFFu, tm0, 2));
        tm1 = fmaxf(tm1, __shfl_xor_sync(0xFFFFFFFFu, tm1, 1));
        tm1 = fmaxf(tm1, __shfl_xor_sync(0xFFFFFFFFu, tm1, 2));
        float nm0 = fmaxf(m0, tm0), nm1 = fmaxf(m1, tm1);
        float al0 = __expf(m0 - nm0), al1 = __expf(m1 - nm1);
        m0 = nm0; m1 = nm1;
        float sum0 = 0.f, sum1 = 0.f;
        #pragma unroll
        for (int j = 0; j < 8; j++) {
            sacc[j][0] = __expf(sacc[j][0] - m0); sum0 += sacc[j][0];
            sacc[j][1] = __expf(sacc[j][1] - m0); sum0 += sacc[j][1];
            sacc[j][2] = __expf(sacc[j][2] - m1); sum1 += sacc[j][2];
            sacc[j][3] = __expf(sacc[j][3] - m1); sum1 += sacc[j][3];
        }
        sum0 += __shfl_xor_sync(0xFFFFFFFFu, sum0, 1);
        sum0 += __shfl_xor_sync(0xFFFFFFFFu, sum0, 2);
        sum1 += __shfl_xor_sync(0xFFFFFFFFu, sum1, 1);
        sum1 += __shfl_xor_sync(0xFFFFFFFFu, sum1, 2);
        l0 = l0 * al0 + sum0;
        l1 = l1 * al1 + sum1;
        #pragma unroll
        for (int d = 0; d < 8; d++) {
            oacc[d][0] *= al0; oacc[d][1] *= al0;
            oacc[d][2] *= al1; oacc[d][3] *= al1;
        }

        uint32_t vB = sb + KV_TILE_B;
        #pragma unroll
        for (int kc2 = 0; kc2 < 4; kc2++) {
            int j0 = 2 * kc2, j1 = j0 + 1;
            uint32_t pl0, pl1, pl2, pl3;
            uint32_t pa0 = split_h(sacc[j0][0], sacc[j0][1], pl0);
            uint32_t pa1 = split_h(sacc[j0][2], sacc[j0][3], pl1);
            uint32_t pa2 = split_h(sacc[j1][0], sacc[j1][1], pl2);
            uint32_t pa3 = split_h(sacc[j1][2], sacc[j1][3], pl3);
            uint32_t vCol = (uint32_t)((kc2 * 16 + coloff) * 2);
            #pragma unroll
            for (int do2 = 0; do2 < 4; do2++) {
                uint32_t vh[4];
                uint32_t vRow = (uint32_t)((do2 * 16 + rowoff) * (KSTR * 2));
                ldsm4(vh, vB + vRow + vCol);
                mma4h(oacc[2*do2],   pa0,pa1,pa2,pa3, vh[0], vh[1]);
                mma4h(oacc[2*do2+1], pa0,pa1,pa2,pa3, vh[2], vh[3]);
                mma4h(oacc[2*do2],   pl0,pl1,pl2,pl3, vh[0], vh[1]);
                mma4h(oacc[2*do2+1], pl0,pl1,pl2,pl3, vh[2], vh[3]);
            }
        }
    }

    // FIX: all warps must finish their last PV ldsm/mma before O-staging
    // overwrites the stage-1 V region (overlaps Os since KV stages shrank).
    __syncthreads();

    float* Os = (float*)(smem + STAGE0_OFF);
    float linv0 = 1.f / l0, linv1 = 1.f / l1;
    int r0q = wbase + (lane >> 2);
    int ddc = (lane & 3) * 2;
    #pragma unroll
    for (int d = 0; d < 8; d++) {
        Os[(d * 8 + ddc)     * OSTR + r0q]     = oacc[d][0] * linv0;
        Os[(d * 8 + ddc + 1) * OSTR + r0q]     = oacc[d][1] * linv0;
        Os[(d * 8 + ddc)     * OSTR + r0q + 8] = oacc[d][2] * linv1;
        Os[(d * 8 + ddc + 1) * OSTR + r0q + 8] = oacc[d][3] * linv1;
    }
    __syncthreads();

    // coop write: fp16 hi/lo ao to [b][n][c]
    {
        int q = tid >> 1;
        int ddb = (tid & 1) * 32;
        uint32_t hb[16], lb[16];
        #pragma unroll
        for (int d = 0; d < 32; d += 2) {
            float f0 = Os[(ddb + d)     * OSTR + q];
            float f1 = Os[(ddb + d + 1) * OSTR + q];
            uint32_t lp;
            hb[d >> 1] = split_h(f0, f1, lp);
            lb[d >> 1] = lp;
        }
        size_t base = ((size_t)b * NHW + qt * 128 + q) * NC + h * 64 + ddb;
        #pragma unroll
        for (int u = 0; u < 4; u++) {
            *(uint4*)(g_aoh + base + u * 8) = *(uint4*)&hb[u * 4];
            *(uint4*)(g_aol + base + u * 8) = *(uint4*)&lb[u * 4];
        }
    }
}

// ---------------------------------------------------------------------------
extern "C" void kernel_launch(void* const* d_in, const int* in_sizes, int n_in,
                              void* d_out, int out_size) {
    const float* x      = (const float*)d_in[0];
    const float* gn_w   = (const float*)d_in[1];
    const float* gn_b   = (const float*)d_in[2];
    const float* qkv_w  = (const float*)d_in[3];
    const float* qkv_b  = (const float*)d_in[4];
    const float* proj_w = (const float*)d_in[5];
    const float* proj_b = (const float*)d_in[6];
    float* out = (float*)d_out;

    cudaFuncSetAttribute(qkv_fp16, cudaFuncAttributeMaxDynamicSharedMemorySize, PJ_SMEM);
    cudaFuncSetAttribute(proj_fp16, cudaFuncAttributeMaxDynamicSharedMemorySize, PJ_SMEM);
    cudaFuncSetAttribute(attn_mma, cudaFuncAttributeMaxDynamicSharedMemorySize, ATTN_SMEM);

    __half *qwh, *pwh, *xh, *xl, *aoh, *aol, *qkvh, *qkvl;
    cudaGetSymbolAddress((void**)&qwh, g_qwh);
    cudaGetSymbolAddress((void**)&pwh, g_pwh);
    cudaGetSymbolAddress((void**)&xh,  g_xh);
    cudaGetSymbolAddress((void**)&xl,  g_xl);
    cudaGetSymbolAddress((void**)&aoh, g_aoh);
    cudaGetSymbolAddress((void**)&aol, g_aol);
    cudaGetSymbolAddress((void**)&qkvh, g_qkvh);
    cudaGetSymbolAddress((void**)&qkvl, g_qkvl);

    // 1. GroupNorm fused with transpose+fp16 hi/lo convert -> g_xh/g_xl
    gn_convert<<<NB * 8, 512>>>(x, gn_w, gn_b, xh, xl);
    // 2. Weight conversion (fp16 single)
    convert_wh<<<(QC * NC + 255) / 256, 256>>>(qkv_w, qwh, QC * NC);
    convert_wh<<<(NC * NC + 255) / 256, 256>>>(proj_w, pwh, NC * NC);
    // 3. QKV GEMM fp16 2-pass, writes fp16 hi/lo (Q scaled)
    qkv_fp16<<<dim3(NHW / 64, QC / 128, NB), 128, PJ_SMEM>>>(
        qwh, xh, xl, qkv_b, qkvh, qkvl);
    // 4. Flash attention fp16 (Q/P exact hi/lo, K/V hi only)
    attn_mma<<<dim3(NHW / 128, NHEADS, NB), 256, ATTN_SMEM>>>();
    // 5. Proj GEMM fp16 2-pass + bias + residual
    proj_fp16<<<dim3(NHW / 64, NC / 128, NB), 128, PJ_SMEM>>>(
        pwh, aoh, aol, proj_b, x, out);
}

// round 15
// speedup vs baseline: 2.2388x; 1.5238x over previous
#include <cuda_runtime.h>
#include <cuda_fp16.h>
#include <cstdint>
#include <math.h>

// Problem constants
#define NB     16
#define NC     512
#define NHW    1024
#define NHEADS 8
#define ND     64
#define QC     1536     // 3*NC
#define GN_EPS 1e-5f

// ===========================================================================
// Warp-level MMA helpers (sm_80+ paths — legal on base sm_100)
// ===========================================================================
__device__ __forceinline__ uint32_t smem_to_u32(const void* p) {
    uint32_t a;
    asm("{ .reg .u64 t; cvta.to.shared.u64 t, %1; cvt.u32.u64 %0, t; }" : "=r"(a) : "l"(p));
    return a;
}
__device__ __forceinline__ void ldsm4(uint32_t* r, uint32_t addr) {
    asm volatile("ldmatrix.sync.aligned.m8n8.x4.shared.b16 {%0,%1,%2,%3}, [%4];"
                 : "=r"(r[0]), "=r"(r[1]), "=r"(r[2]), "=r"(r[3]) : "r"(addr));
}
__device__ __forceinline__ void ldsm4t(uint32_t* r, uint32_t addr) {
    asm volatile("ldmatrix.sync.aligned.m8n8.x4.trans.shared.b16 {%0,%1,%2,%3}, [%4];"
                 : "=r"(r[0]), "=r"(r[1]), "=r"(r[2]), "=r"(r[3]) : "r"(addr));
}
__device__ __forceinline__ void mma_fp16(float* d, const uint32_t* a, const uint32_t* b) {
    asm volatile("mma.sync.aligned.m16n8k16.row.col.f32.f16.f16.f32 "
                 "{%0,%1,%2,%3}, {%4,%5,%6,%7}, {%8,%9}, {%0,%1,%2,%3};"
                 : "+f"(d[0]), "+f"(d[1]), "+f"(d[2]), "+f"(d[3])
                 : "r"(a[0]), "r"(a[1]), "r"(a[2]), "r"(a[3]), "r"(b[0]), "r"(b[1]));
}
__device__ __forceinline__ void mma4h(float* d, uint32_t a0, uint32_t a1, uint32_t a2,
                                      uint32_t a3, uint32_t b0, uint32_t b1) {
    asm volatile("mma.sync.aligned.m16n8k16.row.col.f32.f16.f16.f32 "
                 "{%0,%1,%2,%3}, {%4,%5,%6,%7}, {%8,%9}, {%0,%1,%2,%3};"
                 : "+f"(d[0]), "+f"(d[1]), "+f"(d[2]), "+f"(d[3])
                 : "r"(a0), "r"(a1), "r"(a2), "r"(a3), "r"(b0), "r"(b1));
}
__device__ __forceinline__ void cp_async16(uint32_t daddr, const void* g) {
    asm volatile("cp.async.cg.shared.global [%0], [%1], 16;" :: "r"(daddr), "l"(g));
}
#define CP_COMMIT() asm volatile("cp.async.commit_group;" ::: "memory")
#define CP_WAIT(N)  asm volatile("cp.async.wait_group %0;" :: "n"(N) : "memory")

// pack two fp32 -> f16x2 (element0 in low half)
__device__ __forceinline__ uint32_t packhf(float lo, float hi) {
    uint32_t r;
    asm("cvt.rn.f16x2.f32 %0, %1, %2;" : "=r"(r) : "f"(hi), "f"(lo));
    return r;
}

// ===========================================================================
// Scratch (device globals — no allocation allowed)
// ===========================================================================
__device__ __half g_xh  [NB * NHW * NC];      // gn out fp16 [b][n][c]
__device__ __half g_ao  [NB * NHW * NC];      // attn out fp16 [b][n][c]
__device__ __half g_qkv [NB * QC * NHW];      // qkv fp16 [b][o][n] (Q pre-scaled)
__device__ __half g_qw  [QC * NC];            // qkv_w fp16 [o][c]
__device__ __half g_pw  [NC * NC];            // proj_w fp16 [o][c]

// ---------------------------------------------------------------------------
// Kernel 1: GroupNorm fused with transpose+fp16 convert.
// ---------------------------------------------------------------------------
__global__ __launch_bounds__(512) void gn_convert(const float* __restrict__ x,
                                                  const float* __restrict__ gw,
                                                  const float* __restrict__ gb,
                                                  __half* __restrict__ dh) {
    int bg = blockIdx.x;
    int b = bg >> 3, g = bg & 7;
    const float* xp = x + (size_t)(b * NC + g * 64) * NHW;
    const int NE4 = 64 * NHW / 4;
    int tid = threadIdx.x;

    float s = 0.f, s2 = 0.f;
    const float4* xp4 = (const float4*)xp;
    for (int i = tid; i < NE4; i += 512) {
        float4 v = xp4[i];
        s  += v.x + v.y + v.z + v.w;
        s2 += v.x * v.x + v.y * v.y + v.z * v.z + v.w * v.w;
    }
    __shared__ float rs[16], rs2[16];
    #pragma unroll
    for (int o = 16; o > 0; o >>= 1) {
        s  += __shfl_down_sync(0xFFFFFFFFu, s, o);
        s2 += __shfl_down_sync(0xFFFFFFFFu, s2, o);
    }
    int w = tid >> 5, l = tid & 31;
    if (l == 0) { rs[w] = s; rs2[w] = s2; }
    __syncthreads();
    __shared__ float sh_mean, sh_rstd;
    if (tid == 0) {
        float S = 0.f, S2 = 0.f;
        #pragma unroll
        for (int i = 0; i < 16; i++) { S += rs[i]; S2 += rs2[i]; }
        float mean = S * (1.f / 65536.f);
        float var  = S2 * (1.f / 65536.f) - mean * mean;
        sh_mean = mean;
        sh_rstd = rsqrtf(var + GN_EPS);
    }
    __syncthreads();
    float mean = sh_mean, rstd = sh_rstd;

    __shared__ float t[64][33];
    int tcol = tid & 31, trow = tid >> 5;
    int n_l  = tid >> 4;
    int cseg = (tid & 15) * 4;
    float sc[4], bi[4];
    #pragma unroll
    for (int i = 0; i < 4; i++) {
        int c = g * 64 + cseg + i;
        sc[i] = gw[c] * rstd;
        bi[i] = gb[c] - mean * sc[i];
    }

    for (int n0 = 0; n0 < NHW; n0 += 32) {
        __syncthreads();
        #pragma unroll
        for (int i = 0; i < 4; i++) {
            int c = trow + i * 16;
            t[c][tcol] = xp[(size_t)c * NHW + n0 + tcol];
        }
        __syncthreads();
        float f0 = t[cseg + 0][n_l] * sc[0] + bi[0];
        float f1 = t[cseg + 1][n_l] * sc[1] + bi[1];
        float f2 = t[cseg + 2][n_l] * sc[2] + bi[2];
        float f3 = t[cseg + 3][n_l] * sc[3] + bi[3];
        uint32_t h0 = packhf(f0, f1), h1 = packhf(f2, f3);
        size_t ob = ((size_t)b * NHW + n0 + n_l) * NC + g * 64 + cseg;
        *(uint2*)(dh + ob) = make_uint2(h0, h1);
    }
}

// ---------------------------------------------------------------------------
// Convert weights fp32 -> fp16
// ---------------------------------------------------------------------------
__global__ void convert_wh(const float* __restrict__ src, __half* __restrict__ dh, int n) {
    int i = blockIdx.x * 256 + threadIdx.x;
    if (i < n) dh[i] = __float2half(src[i]);
}

// ---------------------------------------------------------------------------
// fp16 single-pass GEMM geometry: CTA 128(o) x 64(n), 4 warps (2x2),
// warp 64x32, k-chunk 64, 144B rows, 2-stage, 54KB smem -> 2 CTAs/SM.
// D = W * X, both single fp16.
// ---------------------------------------------------------------------------
#define PJ_ROW    144
#define PJ_A_TILE (128 * PJ_ROW)            // 18432
#define PJ_B_TILE (64 * PJ_ROW)             // 9216
#define PJ_STAGE  (PJ_A_TILE + PJ_B_TILE)   // 27648
#define PJ_SMEM   (2 * PJ_STAGE)            // 55296

#define H1_MAINLOOP()                                                          \
    auto load_stage = [&](int chunk, int s) {                                  \
        int k0 = chunk * 64;                                                   \
        uint32_t sbase = smem_u + s * PJ_STAGE;                                \
        _Pragma("unroll")                                                      \
        for (int t = 0; t < 8; t++) {          /* A: 1024 cp */                \
            int idx = t * 128 + tid;                                           \
            int r = idx >> 3;                                                  \
            int ch = idx & 7;                                                  \
            cp_async16(sbase + r * PJ_ROW + ch * 16,                           \
                       a0 + (size_t)r * NC + k0 + ch * 8);                     \
        }                                                                      \
        _Pragma("unroll")                                                      \
        for (int t = 0; t < 4; t++) {          /* B: 512 cp */                 \
            int idx = t * 128 + tid;                                           \
            int r = idx >> 3;                                                  \
            int ch = idx & 7;                                                  \
            cp_async16(sbase + PJ_A_TILE + r * PJ_ROW + ch * 16,               \
                       b0 + (size_t)r * NC + k0 + ch * 8);                     \
        }                                                                      \
        CP_COMMIT();                                                           \
    };                                                                         \
    float acc[4][4][4] = {};                                                   \
    uint32_t aLane = (uint32_t)((lane & 15) * PJ_ROW + (lane >> 4) * 16);      \
    uint32_t bLane = (uint32_t)(((lane & 7) + ((lane >> 4) << 3)) * PJ_ROW +   \
                                ((lane >> 3) & 1) * 16);                       \
    load_stage(0, 0);                                                          \
    _Pragma("unroll 1")                                                        \
    for (int c = 0; c < 8; c++) {                                              \
        if (c + 1 < 8) { load_stage(c + 1, (c + 1) & 1); CP_WAIT(1); }         \
        else { CP_WAIT(0); }                                                   \
        __syncthreads();                                                       \
        uint32_t sb = smem_u + (c & 1) * PJ_STAGE;                             \
        uint32_t offA = sb + (wm * 64) * PJ_ROW + aLane;                       \
        uint32_t offB = sb + PJ_A_TILE + (wn * 32) * PJ_ROW + bLane;           \
        _Pragma("unroll")                                                      \
        for (int ks = 0; ks < 4; ks++) {                                       \
            uint32_t ko = ks * 32;                                             \
            uint32_t af[4][4], bf[2][4];                                       \
            _Pragma("unroll")                                                  \
            for (int i = 0; i < 4; i++) ldsm4(af[i], offA + i * 16 * PJ_ROW + ko);\
            _Pragma("unroll")                                                  \
            for (int g = 0; g < 2; g++) ldsm4(bf[g], offB + g * 16 * PJ_ROW + ko);\
            _Pragma("unroll")                                                  \
            for (int i = 0; i < 4; i++)                                        \
                _Pragma("unroll")                                              \
                for (int j = 0; j < 4; j++)                                    \
                    mma_fp16(acc[i][j], af[i], &bf[j >> 1][(j & 1) * 2]);      \
        }                                                                      \
        __syncthreads();                                                       \
    }

// QKV: single-pass fp16, writes fp16 in [b][o][n], Q rows scaled by 0.125
__global__ __launch_bounds__(128, 2) void qkv_fp16(
        const __half* __restrict__ W, const __half* __restrict__ X,
        const float* __restrict__ bias, __half* __restrict__ outq) {
    extern __shared__ char smem[];
    uint32_t smem_u = smem_to_u32(smem);
    int tid = threadIdx.x;
    int warp = tid >> 5, lane = tid & 31;
    int wm = warp & 1, wn = warp >> 1;
    int n0 = blockIdx.x * 64;
    int o0 = blockIdx.y * 128;
    int b  = blockIdx.z;

    const __half* a0 = W + (size_t)o0 * NC;
    const __half* b0 = X + ((size_t)b * NHW + n0) * NC;

    H1_MAINLOOP();

    int r0 = lane >> 2, c0 = (lane & 3) * 2;
    #pragma unroll
    for (int i = 0; i < 4; i++) {
        #pragma unroll
        for (int half = 0; half < 2; half++) {
            int o = o0 + wm * 64 + i * 16 + r0 + half * 8;
            float bi = bias[o];
            float scq = (o < NC) ? 0.125f : 1.0f;
            size_t rowb = ((size_t)b * QC + o) * NHW + n0 + wn * 32 + c0;
            #pragma unroll
            for (int j = 0; j < 4; j++) {
                float v0 = (acc[i][j][half * 2]     + bi) * scq;
                float v1 = (acc[i][j][half * 2 + 1] + bi) * scq;
                *(uint32_t*)(outq + rowb + j * 8) = packhf(v0, v1);
            }
        }
    }
}

// Proj: single-pass fp16, fp32 out + bias + residual
__global__ __launch_bounds__(128, 2) void proj_fp16(
        const __half* __restrict__ W, const __half* __restrict__ AO,
        const float* __restrict__ bias, const float* __restrict__ residual,
        float* __restrict__ out) {
    extern __shared__ char smem[];
    uint32_t smem_u = smem_to_u32(smem);
    int tid = threadIdx.x;
    int warp = tid >> 5, lane = tid & 31;
    int wm = warp & 1, wn = warp >> 1;
    int n0 = blockIdx.x * 64;
    int o0 = blockIdx.y * 128;
    int b  = blockIdx.z;

    const __half* a0 = W + (size_t)o0 * NC;
    const __half* b0 = AO + ((size_t)b * NHW + n0) * NC;

    H1_MAINLOOP();

    int r0 = lane >> 2, c0 = (lane & 3) * 2;
    #pragma unroll
    for (int i = 0; i < 4; i++) {
        #pragma unroll
        for (int half = 0; half < 2; half++) {
            int o = o0 + wm * 64 + i * 16 + r0 + half * 8;
            float bi = bias[o];
            size_t rowb = ((size_t)b * NC + o) * NHW + n0 + wn * 32 + c0;
            #pragma unroll
            for (int j = 0; j < 4; j++) {
                float v0 = acc[i][j][half * 2]     + bi;
                float v1 = acc[i][j][half * 2 + 1] + bi;
                size_t off = rowb + j * 8;
                float2 rr = *(const float2*)&residual[off];
                *(float2*)&out[off] = make_float2(v0 + rr.x, v1 + rr.y);
            }
        }
    }
}

// ---------------------------------------------------------------------------
// Flash attention fp16 single: S = Q·K, O = P·V (all single fp16).
// Keeps the R14 pre-O-staging __syncthreads() (O region overlaps KV stages).
// ---------------------------------------------------------------------------
#define QSTR 136
#define KSTR 72
#define OSTR 132
#define Q_BYTES   17408
#define KV_TILE_B 9216
#define STAGE0_OFF Q_BYTES
#define KV_STAGE_B (2 * KV_TILE_B)
#define ATTN_SMEM (STAGE0_OFF + 2 * KV_STAGE_B)   // 54272

__global__ __launch_bounds__(256, 2) void attn_mma() {
    extern __shared__ char smem[];
    uint32_t smem_u = smem_to_u32(smem);
    int tid  = threadIdx.x;
    int warp = tid >> 5, lane = tid & 31;
    int wbase = warp * 16;
    int qt = blockIdx.x, h = blockIdx.y, b = blockIdx.z;

    const __half* gq = g_qkv + ((size_t)b * QC + h * ND) * NHW;
    const __half* gk = g_qkv + ((size_t)b * QC + NC + h * ND) * NHW;
    const __half* gv = g_qkv + ((size_t)b * QC + 2 * NC + h * ND) * NHW;
    const __half* kvsrc[2] = {gk, gv};

    int rowoff = ((lane >> 4) << 3) + (lane & 7);
    int coloff = ((lane >> 3) & 1) * 8;

    auto load_stage = [&](int kt, int s) {
        uint32_t sb = smem_u + STAGE0_OFF + s * KV_STAGE_B;
        #pragma unroll
        for (int k = 0; k < 4; k++) {
            int c = tid + k * 256;
            int tile = c >> 9, row = (c >> 3) & 63, ch = c & 7;
            cp_async16(sb + tile * KV_TILE_B + row * (KSTR * 2) + ch * 16,
                       kvsrc[tile] + (size_t)row * NHW + kt * 64 + ch * 8);
        }
        CP_COMMIT();
    };

    // preload Q (single tile, 1024 cp)
    {
        #pragma unroll
        for (int k = 0; k < 4; k++) {
            int c = tid + k * 256;
            int row = (c >> 4) & 63, ch = c & 15;
            cp_async16(smem_u + row * (QSTR * 2) + ch * 16,
                       gq + (size_t)row * NHW + qt * 128 + ch * 8);
        }
    }
    load_stage(0, 0);

    float m0 = -1e30f, m1 = -1e30f, l0 = 0.f, l1 = 0.f;
    float oacc[8][4] = {};

    uint32_t qAddr = smem_u + (uint32_t)(rowoff * (QSTR * 2) + (wbase + coloff) * 2);

    #pragma unroll 1
    for (int kt = 0; kt < 16; kt++) {
        CP_WAIT(0);
        __syncthreads();
        if (kt < 15) load_stage(kt + 1, (kt + 1) & 1);

        uint32_t sb = smem_u + STAGE0_OFF + (kt & 1) * KV_STAGE_B;
        float sacc[8][4] = {};
        #pragma unroll
        for (int kc = 0; kc < 4; kc++) {
            uint32_t qh[4];
            ldsm4t(qh, qAddr + kc * 16 * (QSTR * 2));
            uint32_t kBase = sb + (uint32_t)((kc * 16 + rowoff) * (KSTR * 2) + coloff * 2);
            #pragma unroll
            for (int ko2 = 0; ko2 < 4; ko2++) {
                uint32_t kh[4];
                ldsm4t(kh, kBase + ko2 * 32);
                mma4h(sacc[2*ko2],   qh[0],qh[1],qh[2],qh[3], kh[0], kh[2]);
                mma4h(sacc[2*ko2+1], qh[0],qh[1],qh[2],qh[3], kh[1], kh[3]);
            }
        }

        float tm0 = -1e30f, tm1 = -1e30f;
        #pragma unroll
        for (int j = 0; j < 8; j++) {
            tm0 = fmaxf(tm0, fmaxf(sacc[j][0], sacc[j][1]));
            tm1 = fmaxf(tm1, fmaxf(sacc[j][2], sacc[j][3]));
        }
        tm0 = fmaxf(tm0, __shfl_xor_sync(0xFFFFFFFFu, tm0, 1));
        tm0 = fmaxf(tm0, __shfl_xor_sync(0xFFFFFFFFu, tm0, 2));
        tm1 = fmaxf(tm1, __shfl_xor_sync(0xFFFFFFFFu, tm1, 1));
        tm1 = fmaxf(tm1, __shfl_xor_sync(0xFFFFFFFFu, tm1, 2));
        float nm0 = fmaxf(m0, tm0), nm1 = fmaxf(m1, tm1);
        float al0 = __expf(m0 - nm0), al1 = __expf(m1 - nm1);
        m0 = nm0; m1 = nm1;
        float sum0 = 0.f, sum1 = 0.f;
        #pragma unroll
        for (int j = 0; j < 8; j++) {
            sacc[j][0] = __expf(sacc[j][0] - m0); sum0 += sacc[j][0];
            sacc[j][1] = __expf(sacc[j][1] - m0); sum0 += sacc[j][1];
            sacc[j][2] = __expf(sacc[j][2] - m1); sum1 += sacc[j][2];
            sacc[j][3] = __expf(sacc[j][3] - m1); sum1 += sacc[j][3];
        }
        sum0 += __shfl_xor_sync(0xFFFFFFFFu, sum0, 1);
        sum0 += __shfl_xor_sync(0xFFFFFFFFu, sum0, 2);
        sum1 += __shfl_xor_sync(0xFFFFFFFFu, sum1, 1);
        sum1 += __shfl_xor_sync(0xFFFFFFFFu, sum1, 2);
        l0 = l0 * al0 + sum0;
        l1 = l1 * al1 + sum1;
        #pragma unroll
        for (int d = 0; d < 8; d++) {
            oacc[d][0] *= al0; oacc[d][1] *= al0;
            oacc[d][2] *= al1; oacc[d][3] *= al1;
        }

        uint32_t vB = sb + KV_TILE_B;
        #pragma unroll
        for (int kc2 = 0; kc2 < 4; kc2++) {
            int j0 = 2 * kc2, j1 = j0 + 1;
            uint32_t pa0 = packhf(sacc[j0][0], sacc[j0][1]);
            uint32_t pa1 = packhf(sacc[j0][2], sacc[j0][3]);
            uint32_t pa2 = packhf(sacc[j1][0], sacc[j1][1]);
            uint32_t pa3 = packhf(sacc[j1][2], sacc[j1][3]);
            uint32_t vCol = (uint32_t)((kc2 * 16 + coloff) * 2);
            #pragma unroll
            for (int do2 = 0; do2 < 4; do2++) {
                uint32_t vh[4];
                uint32_t vRow = (uint32_t)((do2 * 16 + rowoff) * (KSTR * 2));
                ldsm4(vh, vB + vRow + vCol);
                mma4h(oacc[2*do2],   pa0,pa1,pa2,pa3, vh[0], vh[1]);
                mma4h(oacc[2*do2+1], pa0,pa1,pa2,pa3, vh[2], vh[3]);
            }
        }
    }

    // All warps must retire their last PV ldsm/mma before O-staging
    // overwrites the KV stage regions (Os overlaps both stages).
    __syncthreads();

    float* Os = (float*)(smem + STAGE0_OFF);
    float linv0 = 1.f / l0, linv1 = 1.f / l1;
    int r0q = wbase + (lane >> 2);
    int ddc = (lane & 3) * 2;
    #pragma unroll
    for (int d = 0; d < 8; d++) {
        Os[(d * 8 + ddc)     * OSTR + r0q]     = oacc[d][0] * linv0;
        Os[(d * 8 + ddc + 1) * OSTR + r0q]     = oacc[d][1] * linv0;
        Os[(d * 8 + ddc)     * OSTR + r0q + 8] = oacc[d][2] * linv1;
        Os[(d * 8 + ddc + 1) * OSTR + r0q + 8] = oacc[d][3] * linv1;
    }
    __syncthreads();

    // coop write: fp16 ao to [b][n][c]
    {
        int q = tid >> 1;
        int ddb = (tid & 1) * 32;
        uint32_t hb[16];
        #pragma unroll
        for (int d = 0; d < 32; d += 2) {
            float f0 = Os[(ddb + d)     * OSTR + q];
            float f1 = Os[(ddb + d + 1) * OSTR + q];
            hb[d >> 1] = packhf(f0, f1);
        }
        size_t base = ((size_t)b * NHW + qt * 128 + q) * NC + h * 64 + ddb;
        #pragma unroll
        for (int u = 0; u < 4; u++)
            *(uint4*)(g_ao + base + u * 8) = *(uint4*)&hb[u * 4];
    }
}

// ---------------------------------------------------------------------------
extern "C" void kernel_launch(void* const* d_in, const int* in_sizes, int n_in,
                              void* d_out, int out_size) {
    const float* x      = (const float*)d_in[0];
    const float* gn_w   = (const float*)d_in[1];
    const float* gn_b   = (const float*)d_in[2];
    const float* qkv_w  = (const float*)d_in[3];
    const float* qkv_b  = (const float*)d_in[4];
    const float* proj_w = (const float*)d_in[5];
    const float* proj_b = (const float*)d_in[6];
    float* out = (float*)d_out;

    cudaFuncSetAttribute(qkv_fp16, cudaFuncAttributeMaxDynamicSharedMemorySize, PJ_SMEM);
    cudaFuncSetAttribute(proj_fp16, cudaFuncAttributeMaxDynamicSharedMemorySize, PJ_SMEM);
    cudaFuncSetAttribute(attn_mma, cudaFuncAttributeMaxDynamicSharedMemorySize, ATTN_SMEM);

    __half *qw, *pw, *xh, *ao, *qkv;
    cudaGetSymbolAddress((void**)&qw, g_qw);
    cudaGetSymbolAddress((void**)&pw, g_pw);
    cudaGetSymbolAddress((void**)&xh, g_xh);
    cudaGetSymbolAddress((void**)&ao, g_ao);
    cudaGetSymbolAddress((void**)&qkv, g_qkv);

    // 1. GroupNorm fused with transpose+fp16 convert -> g_xh [b][n][c]
    gn_convert<<<NB * 8, 512>>>(x, gn_w, gn_b, xh);
    // 2. Weight conversion (fp16)
    convert_wh<<<(QC * NC + 255) / 256, 256>>>(qkv_w, qw, QC * NC);
    convert_wh<<<(NC * NC + 255) / 256, 256>>>(proj_w, pw, NC * NC);
    // 3. QKV GEMM fp16 single-pass, writes fp16 (Q scaled)
    qkv_fp16<<<dim3(NHW / 64, QC / 128, NB), 128, PJ_SMEM>>>(
        qw, xh, qkv_b, qkv);
    // 4. Flash attention fp16 single
    attn_mma<<<dim3(NHW / 128, NHEADS, NB), 256, ATTN_SMEM>>>();
    // 5. Proj GEMM fp16 single-pass + bias + residual
    proj_fp16<<<dim3(NHW / 64, NC / 128, NB), 128, PJ_SMEM>>>(
        pw, ao, proj_b, x, out);
}

// round 16
// speedup vs baseline: 2.2391x; 1.0001x over previous
#include <cuda_runtime.h>
#include <cuda_fp16.h>
#include <cstdint>
#include <math.h>

// Problem constants
#define NB     16
#define NC     512
#define NHW    1024
#define NHEADS 8
#define ND     64
#define QC     1536     // 3*NC
#define GN_EPS 1e-5f

// ===========================================================================
// Warp-level MMA helpers (sm_80+ paths — legal on base sm_100)
// ===========================================================================
__device__ __forceinline__ uint32_t smem_to_u32(const void* p) {
    uint32_t a;
    asm("{ .reg .u64 t; cvta.to.shared.u64 t, %1; cvt.u32.u64 %0, t; }" : "=r"(a) : "l"(p));
    return a;
}
__device__ __forceinline__ void ldsm4(uint32_t* r, uint32_t addr) {
    asm volatile("ldmatrix.sync.aligned.m8n8.x4.shared.b16 {%0,%1,%2,%3}, [%4];"
                 : "=r"(r[0]), "=r"(r[1]), "=r"(r[2]), "=r"(r[3]) : "r"(addr));
}
__device__ __forceinline__ void ldsm4t(uint32_t* r, uint32_t addr) {
    asm volatile("ldmatrix.sync.aligned.m8n8.x4.trans.shared.b16 {%0,%1,%2,%3}, [%4];"
                 : "=r"(r[0]), "=r"(r[1]), "=r"(r[2]), "=r"(r[3]) : "r"(addr));
}
__device__ __forceinline__ void mma_fp16(float* d, const uint32_t* a, const uint32_t* b) {
    asm volatile("mma.sync.aligned.m16n8k16.row.col.f32.f16.f16.f32 "
                 "{%0,%1,%2,%3}, {%4,%5,%6,%7}, {%8,%9}, {%0,%1,%2,%3};"
                 : "+f"(d[0]), "+f"(d[1]), "+f"(d[2]), "+f"(d[3])
                 : "r"(a[0]), "r"(a[1]), "r"(a[2]), "r"(a[3]), "r"(b[0]), "r"(b[1]));
}
__device__ __forceinline__ void mma4h(float* d, uint32_t a0, uint32_t a1, uint32_t a2,
                                      uint32_t a3, uint32_t b0, uint32_t b1) {
    asm volatile("mma.sync.aligned.m16n8k16.row.col.f32.f16.f16.f32 "
                 "{%0,%1,%2,%3}, {%4,%5,%6,%7}, {%8,%9}, {%0,%1,%2,%3};"
                 : "+f"(d[0]), "+f"(d[1]), "+f"(d[2]), "+f"(d[3])
                 : "r"(a0), "r"(a1), "r"(a2), "r"(a3), "r"(b0), "r"(b1));
}
__device__ __forceinline__ void cp_async16(uint32_t daddr, const void* g) {
    asm volatile("cp.async.cg.shared.global [%0], [%1], 16;" :: "r"(daddr), "l"(g));
}
#define CP_COMMIT() asm volatile("cp.async.commit_group;" ::: "memory")
#define CP_WAIT(N)  asm volatile("cp.async.wait_group %0;" :: "n"(N) : "memory")

// pack two fp32 -> f16x2 (element0 in low half)
__device__ __forceinline__ uint32_t packhf(float lo, float hi) {
    uint32_t r;
    asm("cvt.rn.f16x2.f32 %0, %1, %2;" : "=r"(r) : "f"(hi), "f"(lo));
    return r;
}

// ===========================================================================
// Scratch (device globals — no allocation allowed)
// ===========================================================================
__device__ __half g_xh  [NB * NHW * NC];      // gn out fp16 [b][n][c]
__device__ __half g_ao  [NB * NHW * NC];      // attn out fp16 [b][n][c]
__device__ __half g_qkv [NB * QC * NHW];      // qkv fp16 [b][o][n] (Q pre-scaled)
__device__ __half g_qw  [QC * NC];            // qkv_w fp16 [o][c]
__device__ __half g_pw  [NC * NC];            // proj_w fp16 [o][c]

// ---------------------------------------------------------------------------
// Kernel 1: GroupNorm fused with transpose+fp16 convert.
// ---------------------------------------------------------------------------
__global__ __launch_bounds__(512) void gn_convert(const float* __restrict__ x,
                                                  const float* __restrict__ gw,
                                                  const float* __restrict__ gb,
                                                  __half* __restrict__ dh) {
    int bg = blockIdx.x;
    int b = bg >> 3, g = bg & 7;
    const float* xp = x + (size_t)(b * NC + g * 64) * NHW;
    const int NE4 = 64 * NHW / 4;
    int tid = threadIdx.x;

    float s = 0.f, s2 = 0.f;
    const float4* xp4 = (const float4*)xp;
    for (int i = tid; i < NE4; i += 512) {
        float4 v = xp4[i];
        s  += v.x + v.y + v.z + v.w;
        s2 += v.x * v.x + v.y * v.y + v.z * v.z + v.w * v.w;
    }
    __shared__ float rs[16], rs2[16];
    #pragma unroll
    for (int o = 16; o > 0; o >>= 1) {
        s  += __shfl_down_sync(0xFFFFFFFFu, s, o);
        s2 += __shfl_down_sync(0xFFFFFFFFu, s2, o);
    }
    int w = tid >> 5, l = tid & 31;
    if (l == 0) { rs[w] = s; rs2[w] = s2; }
    __syncthreads();
    __shared__ float sh_mean, sh_rstd;
    if (tid == 0) {
        float S = 0.f, S2 = 0.f;
        #pragma unroll
        for (int i = 0; i < 16; i++) { S += rs[i]; S2 += rs2[i]; }
        float mean = S * (1.f / 65536.f);
        float var  = S2 * (1.f / 65536.f) - mean * mean;
        sh_mean = mean;
        sh_rstd = rsqrtf(var + GN_EPS);
    }
    __syncthreads();
    float mean = sh_mean, rstd = sh_rstd;

    __shared__ float t[64][33];
    int tcol = tid & 31, trow = tid >> 5;
    int n_l  = tid >> 4;
    int cseg = (tid & 15) * 4;
    float sc[4], bi[4];
    #pragma unroll
    for (int i = 0; i < 4; i++) {
        int c = g * 64 + cseg + i;
        sc[i] = gw[c] * rstd;
        bi[i] = gb[c] - mean * sc[i];
    }

    for (int n0 = 0; n0 < NHW; n0 += 32) {
        __syncthreads();
        #pragma unroll
        for (int i = 0; i < 4; i++) {
            int c = trow + i * 16;
            t[c][tcol] = xp[(size_t)c * NHW + n0 + tcol];
        }
        __syncthreads();
        float f0 = t[cseg + 0][n_l] * sc[0] + bi[0];
        float f1 = t[cseg + 1][n_l] * sc[1] + bi[1];
        float f2 = t[cseg + 2][n_l] * sc[2] + bi[2];
        float f3 = t[cseg + 3][n_l] * sc[3] + bi[3];
        uint32_t h0 = packhf(f0, f1), h1 = packhf(f2, f3);
        size_t ob = ((size_t)b * NHW + n0 + n_l) * NC + g * 64 + cseg;
        *(uint2*)(dh + ob) = make_uint2(h0, h1);
    }
}

// ---------------------------------------------------------------------------
// Convert weights fp32 -> fp16
// ---------------------------------------------------------------------------
__global__ void convert_wh(const float* __restrict__ src, __half* __restrict__ dh, int n) {
    int i = blockIdx.x * 256 + threadIdx.x;
    if (i < n) dh[i] = __float2half(src[i]);
}

// ---------------------------------------------------------------------------
// fp16 single-pass GEMM geometry: CTA 128(o) x 64(n), 4 warps (2x2),
// warp 64x32, k-chunk 64, 144B rows, 2-stage, 54KB smem -> 2 CTAs/SM.
// D = W * X, both single fp16.
// ---------------------------------------------------------------------------
#define PJ_ROW    144
#define PJ_A_TILE (128 * PJ_ROW)            // 18432
#define PJ_B_TILE (64 * PJ_ROW)             // 9216
#define PJ_STAGE  (PJ_A_TILE + PJ_B_TILE)   // 27648
#define PJ_SMEM   (2 * PJ_STAGE)            // 55296

#define H1_MAINLOOP()                                                          \
    auto load_stage = [&](int chunk, int s) {                                  \
        int k0 = chunk * 64;                                                   \
        uint32_t sbase = smem_u + s * PJ_STAGE;                                \
        _Pragma("unroll")                                                      \
        for (int t = 0; t < 8; t++) {          /* A: 1024 cp */                \
            int idx = t * 128 + tid;                                           \
            int r = idx >> 3;                                                  \
            int ch = idx & 7;                                                  \
            cp_async16(sbase + r * PJ_ROW + ch * 16,                           \
                       a0 + (size_t)r * NC + k0 + ch * 8);                     \
        }                                                                      \
        _Pragma("unroll")                                                      \
        for (int t = 0; t < 4; t++) {          /* B: 512 cp */                 \
            int idx = t * 128 + tid;                                           \
            int r = idx >> 3;                                                  \
            int ch = idx & 7;                                                  \
            cp_async16(sbase + PJ_A_TILE + r * PJ_ROW + ch * 16,               \
                       b0 + (size_t)r * NC + k0 + ch * 8);                     \
        }                                                                      \
        CP_COMMIT();                                                           \
    };                                                                         \
    float acc[4][4][4] = {};                                                   \
    uint32_t aLane = (uint32_t)((lane & 15) * PJ_ROW + (lane >> 4) * 16);      \
    uint32_t bLane = (uint32_t)(((lane & 7) + ((lane >> 4) << 3)) * PJ_ROW +   \
                                ((lane >> 3) & 1) * 16);                       \
    load_stage(0, 0);                                                          \
    _Pragma("unroll 1")                                                        \
    for (int c = 0; c < 8; c++) {                                              \
        if (c + 1 < 8) { load_stage(c + 1, (c + 1) & 1); CP_WAIT(1); }         \
        else { CP_WAIT(0); }                                                   \
        __syncthreads();                                                       \
        uint32_t sb = smem_u + (c & 1) * PJ_STAGE;                             \
        uint32_t offA = sb + (wm * 64) * PJ_ROW + aLane;                       \
        uint32_t offB = sb + PJ_A_TILE + (wn * 32) * PJ_ROW + bLane;           \
        _Pragma("unroll")                                                      \
        for (int ks = 0; ks < 4; ks++) {                                       \
            uint32_t ko = ks * 32;                                             \
            uint32_t af[4][4], bf[2][4];                                       \
            _Pragma("unroll")                                                  \
            for (int i = 0; i < 4; i++) ldsm4(af[i], offA + i * 16 * PJ_ROW + ko);\
            _Pragma("unroll")                                                  \
            for (int g = 0; g < 2; g++) ldsm4(bf[g], offB + g * 16 * PJ_ROW + ko);\
            _Pragma("unroll")                                                  \
            for (int i = 0; i < 4; i++)                                        \
                _Pragma("unroll")                                              \
                for (int j = 0; j < 4; j++)                                    \
                    mma_fp16(acc[i][j], af[i], &bf[j >> 1][(j & 1) * 2]);      \
        }                                                                      \
        __syncthreads();                                                       \
    }

// QKV: single-pass fp16, writes fp16 in [b][o][n], Q rows scaled by 0.125
__global__ __launch_bounds__(128, 2) void qkv_fp16(
        const __half* __restrict__ W, const __half* __restrict__ X,
        const float* __restrict__ bias, __half* __restrict__ outq) {
    extern __shared__ char smem[];
    uint32_t smem_u = smem_to_u32(smem);
    int tid = threadIdx.x;
    int warp = tid >> 5, lane = tid & 31;
    int wm = warp & 1, wn = warp >> 1;
    int n0 = blockIdx.x * 64;
    int o0 = blockIdx.y * 128;
    int b  = blockIdx.z;

    const __half* a0 = W + (size_t)o0 * NC;
    const __half* b0 = X + ((size_t)b * NHW + n0) * NC;

    H1_MAINLOOP();

    int r0 = lane >> 2, c0 = (lane & 3) * 2;
    #pragma unroll
    for (int i = 0; i < 4; i++) {
        #pragma unroll
        for (int half = 0; half < 2; half++) {
            int o = o0 + wm * 64 + i * 16 + r0 + half * 8;
            float bi = bias[o];
            float scq = (o < NC) ? 0.125f : 1.0f;
            size_t rowb = ((size_t)b * QC + o) * NHW + n0 + wn * 32 + c0;
            #pragma unroll
            for (int j = 0; j < 4; j++) {
                float v0 = (acc[i][j][half * 2]     + bi) * scq;
                float v1 = (acc[i][j][half * 2 + 1] + bi) * scq;
                *(uint32_t*)(outq + rowb + j * 8) = packhf(v0, v1);
            }
        }
    }
}

// Proj: single-pass fp16, fp32 out + bias + residual
__global__ __launch_bounds__(128, 2) void proj_fp16(
        const __half* __restrict__ W, const __half* __restrict__ AO,
        const float* __restrict__ bias, const float* __restrict__ residual,
        float* __restrict__ out) {
    extern __shared__ char smem[];
    uint32_t smem_u = smem_to_u32(smem);
    int tid = threadIdx.x;
    int warp = tid >> 5, lane = tid & 31;
    int wm = warp & 1, wn = warp >> 1;
    int n0 = blockIdx.x * 64;
    int o0 = blockIdx.y * 128;
    int b  = blockIdx.z;

    const __half* a0 = W + (size_t)o0 * NC;
    const __half* b0 = AO + ((size_t)b * NHW + n0) * NC;

    H1_MAINLOOP();

    int r0 = lane >> 2, c0 = (lane & 3) * 2;
    #pragma unroll
    for (int i = 0; i < 4; i++) {
        #pragma unroll
        for (int half = 0; half < 2; half++) {
            int o = o0 + wm * 64 + i * 16 + r0 + half * 8;
            float bi = bias[o];
            size_t rowb = ((size_t)b * NC + o) * NHW + n0 + wn * 32 + c0;
            #pragma unroll
            for (int j = 0; j < 4; j++) {
                float v0 = acc[i][j][half * 2]     + bi;
                float v1 = acc[i][j][half * 2 + 1] + bi;
                size_t off = rowb + j * 8;
                float2 rr = *(const float2*)&residual[off];
                *(float2*)&out[off] = make_float2(v0 + rr.x, v1 + rr.y);
            }
        }
    }
}

// ---------------------------------------------------------------------------
// Flash attention fp16 single: S = Q·K, O = P·V (all single fp16).
// Keeps the R14 pre-O-staging __syncthreads() (O region overlaps KV stages).
// ---------------------------------------------------------------------------
#define QSTR 136
#define KSTR 72
#define OSTR 132
#define Q_BYTES   17408
#define KV_TILE_B 9216
#define STAGE0_OFF Q_BYTES
#define KV_STAGE_B (2 * KV_TILE_B)
#define ATTN_SMEM (STAGE0_OFF + 2 * KV_STAGE_B)   // 54272

__global__ __launch_bounds__(256, 2) void attn_mma() {
    extern __shared__ char smem[];
    uint32_t smem_u = smem_to_u32(smem);
    int tid  = threadIdx.x;
    int warp = tid >> 5, lane = tid & 31;
    int wbase = warp * 16;
    int qt = blockIdx.x, h = blockIdx.y, b = blockIdx.z;

    const __half* gq = g_qkv + ((size_t)b * QC + h * ND) * NHW;
    const __half* gk = g_qkv + ((size_t)b * QC + NC + h * ND) * NHW;
    const __half* gv = g_qkv + ((size_t)b * QC + 2 * NC + h * ND) * NHW;
    const __half* kvsrc[2] = {gk, gv};

    int rowoff = ((lane >> 4) << 3) + (lane & 7);
    int coloff = ((lane >> 3) & 1) * 8;

    auto load_stage = [&](int kt, int s) {
        uint32_t sb = smem_u + STAGE0_OFF + s * KV_STAGE_B;
        #pragma unroll
        for (int k = 0; k < 4; k++) {
            int c = tid + k * 256;
            int tile = c >> 9, row = (c >> 3) & 63, ch = c & 7;
            cp_async16(sb + tile * KV_TILE_B + row * (KSTR * 2) + ch * 16,
                       kvsrc[tile] + (size_t)row * NHW + kt * 64 + ch * 8);
        }
        CP_COMMIT();
    };

    // preload Q (single tile, 1024 cp)
    {
        #pragma unroll
        for (int k = 0; k < 4; k++) {
            int c = tid + k * 256;
            int row = (c >> 4) & 63, ch = c & 15;
            cp_async16(smem_u + row * (QSTR * 2) + ch * 16,
                       gq + (size_t)row * NHW + qt * 128 + ch * 8);
        }
    }
    load_stage(0, 0);

    float m0 = -1e30f, m1 = -1e30f, l0 = 0.f, l1 = 0.f;
    float oacc[8][4] = {};

    uint32_t qAddr = smem_u + (uint32_t)(rowoff * (QSTR * 2) + (wbase + coloff) * 2);

    #pragma unroll 1
    for (int kt = 0; kt < 16; kt++) {
        CP_WAIT(0);
        __syncthreads();
        if (kt < 15) load_stage(kt + 1, (kt + 1) & 1);

        uint32_t sb = smem_u + STAGE0_OFF + (kt & 1) * KV_STAGE_B;
        float sacc[8][4] = {};
        #pragma unroll
        for (int kc = 0; kc < 4; kc++) {
            uint32_t qh[4];
            ldsm4t(qh, qAddr + kc * 16 * (QSTR * 2));
            uint32_t kBase = sb + (uint32_t)((kc * 16 + rowoff) * (KSTR * 2) + coloff * 2);
            #pragma unroll
            for (int ko2 = 0; ko2 < 4; ko2++) {
                uint32_t kh[4];
                ldsm4t(kh, kBase + ko2 * 32);
                mma4h(sacc[2*ko2],   qh[0],qh[1],qh[2],qh[3], kh[0], kh[2]);
                mma4h(sacc[2*ko2+1], qh[0],qh[1],qh[2],qh[3], kh[1], kh[3]);
            }
        }

        float tm0 = -1e30f, tm1 = -1e30f;
        #pragma unroll
        for (int j = 0; j < 8; j++) {
            tm0 = fmaxf(tm0, fmaxf(sacc[j][0], sacc[j][1]));
            tm1 = fmaxf(tm1, fmaxf(sacc[j][2], sacc[j][3]));
        }
        tm0 = fmaxf(tm0, __shfl_xor_sync(0xFFFFFFFFu, tm0, 1));
        tm0 = fmaxf(tm0, __shfl_xor_sync(0xFFFFFFFFu, tm0, 2));
        tm1 = fmaxf(tm1, __shfl_xor_sync(0xFFFFFFFFu, tm1, 1));
        tm1 = fmaxf(tm1, __shfl_xor_sync(0xFFFFFFFFu, tm1, 2));
        float nm0 = fmaxf(m0, tm0), nm1 = fmaxf(m1, tm1);
        float al0 = __expf(m0 - nm0), al1 = __expf(m1 - nm1);
        m0 = nm0; m1 = nm1;
        float sum0 = 0.f, sum1 = 0.f;
        #pragma unroll
        for (int j = 0; j < 8; j++) {
            sacc[j][0] = __expf(sacc[j][0] - m0); sum0 += sacc[j][0];
            sacc[j][1] = __expf(sacc[j][1] - m0); sum0 += sacc[j][1];
            sacc[j][2] = __expf(sacc[j][2] - m1); sum1 += sacc[j][2];
            sacc[j][3] = __expf(sacc[j][3] - m1); sum1 += sacc[j][3];
        }
        sum0 += __shfl_xor_sync(0xFFFFFFFFu, sum0, 1);
        sum0 += __shfl_xor_sync(0xFFFFFFFFu, sum0, 2);
        sum1 += __shfl_xor_sync(0xFFFFFFFFu, sum1, 1);
        sum1 += __shfl_xor_sync(0xFFFFFFFFu, sum1, 2);
        l0 = l0 * al0 + sum0;
        l1 = l1 * al1 + sum1;
        #pragma unroll
        for (int d = 0; d < 8; d++) {
            oacc[d][0] *= al0; oacc[d][1] *= al0;
            oacc[d][2] *= al1; oacc[d][3] *= al1;
        }

        uint32_t vB = sb + KV_TILE_B;
        #pragma unroll
        for (int kc2 = 0; kc2 < 4; kc2++) {
            int j0 = 2 * kc2, j1 = j0 + 1;
            uint32_t pa0 = packhf(sacc[j0][0], sacc[j0][1]);
            uint32_t pa1 = packhf(sacc[j0][2], sacc[j0][3]);
            uint32_t pa2 = packhf(sacc[j1][0], sacc[j1][1]);
            uint32_t pa3 = packhf(sacc[j1][2], sacc[j1][3]);
            uint32_t vCol = (uint32_t)((kc2 * 16 + coloff) * 2);
            #pragma unroll
            for (int do2 = 0; do2 < 4; do2++) {
                uint32_t vh[4];
                uint32_t vRow = (uint32_t)((do2 * 16 + rowoff) * (KSTR * 2));
                ldsm4(vh, vB + vRow + vCol);
                mma4h(oacc[2*do2],   pa0,pa1,pa2,pa3, vh[0], vh[1]);
                mma4h(oacc[2*do2+1], pa0,pa1,pa2,pa3, vh[2], vh[3]);
            }
        }
    }

    // All warps must retire their last PV ldsm/mma before O-staging
    // overwrites the KV stage regions (Os overlaps both stages).
    __syncthreads();

    float* Os = (float*)(smem + STAGE0_OFF);
    float linv0 = 1.f / l0, linv1 = 1.f / l1;
    int r0q = wbase + (lane >> 2);
    int ddc = (lane & 3) * 2;
    #pragma unroll
    for (int d = 0; d < 8; d++) {
        Os[(d * 8 + ddc)     * OSTR + r0q]     = oacc[d][0] * linv0;
        Os[(d * 8 + ddc + 1) * OSTR + r0q]     = oacc[d][1] * linv0;
        Os[(d * 8 + ddc)     * OSTR + r0q + 8] = oacc[d][2] * linv1;
        Os[(d * 8 + ddc + 1) * OSTR + r0q + 8] = oacc[d][3] * linv1;
    }
    __syncthreads();

    // coop write: fp16 ao to [b][n][c]
    {
        int q = tid >> 1;
        int ddb = (tid & 1) * 32;
        uint32_t hb[16];
        #pragma unroll
        for (int d = 0; d < 32; d += 2) {
            float f0 = Os[(ddb + d)     * OSTR + q];
            float f1 = Os[(ddb + d + 1) * OSTR + q];
            hb[d >> 1] = packhf(f0, f1);
        }
        size_t base = ((size_t)b * NHW + qt * 128 + q) * NC + h * 64 + ddb;
        #pragma unroll
        for (int u = 0; u < 4; u++)
            *(uint4*)(g_ao + base + u * 8) = *(uint4*)&hb[u * 4];
    }
}

// ---------------------------------------------------------------------------
extern "C" void kernel_launch(void* const* d_in, const int* in_sizes, int n_in,
                              void* d_out, int out_size) {
    const float* x      = (const float*)d_in[0];
    const float* gn_w   = (const float*)d_in[1];
    const float* gn_b   = (const float*)d_in[2];
    const float* qkv_w  = (const float*)d_in[3];
    const float* qkv_b  = (const float*)d_in[4];
    const float* proj_w = (const float*)d_in[5];
    const float* proj_b = (const float*)d_in[6];
    float* out = (float*)d_out;

    cudaFuncSetAttribute(qkv_fp16, cudaFuncAttributeMaxDynamicSharedMemorySize, PJ_SMEM);
    cudaFuncSetAttribute(proj_fp16, cudaFuncAttributeMaxDynamicSharedMemorySize, PJ_SMEM);
    cudaFuncSetAttribute(attn_mma, cudaFuncAttributeMaxDynamicSharedMemorySize, ATTN_SMEM);

    __half *qw, *pw, *xh, *ao, *qkv;
    cudaGetSymbolAddress((void**)&qw, g_qw);
    cudaGetSymbolAddress((void**)&pw, g_pw);
    cudaGetSymbolAddress((void**)&xh, g_xh);
    cudaGetSymbolAddress((void**)&ao, g_ao);
    cudaGetSymbolAddress((void**)&qkv, g_qkv);

    // 1. GroupNorm fused with transpose+fp16 convert -> g_xh [b][n][c]
    gn_convert<<<NB * 8, 512>>>(x, gn_w, gn_b, xh);
    // 2. Weight conversion (fp16)
    convert_wh<<<(QC * NC + 255) / 256, 256>>>(qkv_w, qw, QC * NC);
    convert_wh<<<(NC * NC + 255) / 256, 256>>>(proj_w, pw, NC * NC);
    // 3. QKV GEMM fp16 single-pass, writes fp16 (Q scaled)
    qkv_fp16<<<dim3(NHW / 64, QC / 128, NB), 128, PJ_SMEM>>>(
        qw, xh, qkv_b, qkv);
    // 4. Flash attention fp16 single
    attn_mma<<<dim3(NHW / 128, NHEADS, NB), 256, ATTN_SMEM>>>();
    // 5. Proj GEMM fp16 single-pass + bias + residual
    proj_fp16<<<dim3(NHW / 64, NC / 128, NB), 128, PJ_SMEM>>>(
        pw, ao, proj_b, x, out);
}